// round 8
// baseline (speedup 1.0000x reference)
#include <cuda_runtime.h>
#include <cuda_fp16.h>
#include <cstdint>

// ---------------------------------------------------------------------------
// Problem constants
// ---------------------------------------------------------------------------
namespace {
constexpr int kB  = 8;
constexpr int kL  = 1024;
constexpr int kD  = 512;
constexpr int kH  = 8;
constexpr int kHD = 64;
constexpr int kBH = kB * kH;                 // 64
constexpr int kOutElems  = kB * kL * kD;     // 4,194,304
constexpr int kAttnElems = kBH * kL * kL;    // 67,108,864

// mma.sync GEMM smem: 2 buffers x (As[128][36] + Bs[128][36]) floats
constexpr int kGemmBufFloats  = 128 * 36;                   // 4,608
constexpr int kGemmSmemBytes  = 4 * kGemmBufFloats * 4;     // 73,728 B

// fused attention kernel smem (floats):
//   Qs [64][68] | big: max(Eseg[192][68], K[128][68], V^T[64][132]) | panel
//   region (fp16 [64][200] / Pchunk f32 [64][68]) | rs[128] | rsinv[64]
constexpr int kQsFloats    = 64 * 68;        // 4,352
constexpr int kBigFloats   = 192 * 68;       // 13,056
constexpr int kPanFloats   = 6400;           // 64*200 halves
constexpr int kFusedFloats = kQsFloats + kBigFloats + kPanFloats + 128 + 64;
constexpr int kFusedSmemBytes = kFusedFloats * 4;           // 96,000 B -> 2 CTA/SM

// fold softmax 1/sqrt(64) and log2(e) into q so attention does exp2(qk+qe)
constexpr float kQScale = 0.125f * 1.4426950408889634f;
}

// Scratch (device globals; no allocations allowed)
__device__ float g_q[kBH * kL * kHD];
__device__ float g_k[kBH * kL * kHD];
__device__ float g_v[kBH * kL * kHD];
__device__ float g_ctx[kBH * kL * kHD];
__device__ float g_wt[4 * kD * kD];          // W^T for q,k,v,o
__device__ float g_fb[kAttnElems];           // fallback attn sink (never expected)

// ---------------------------------------------------------------------------
// Helpers
// ---------------------------------------------------------------------------
__device__ __forceinline__ uint32_t f2tf32(float x) {
    uint32_t r;
    asm("cvt.rna.tf32.f32 %0, %1;" : "=r"(r) : "f"(x));
    return r;
}
__device__ __forceinline__ float tf32f(float x) {
    return __uint_as_float(f2tf32(x));
}
__device__ __forceinline__ void mma_tf32(float* c, const uint32_t* a, const uint32_t* b) {
    asm volatile(
        "mma.sync.aligned.m16n8k8.row.col.f32.tf32.tf32.f32 "
        "{%0,%1,%2,%3}, {%4,%5,%6,%7}, {%8,%9}, {%0,%1,%2,%3};"
        : "+f"(c[0]), "+f"(c[1]), "+f"(c[2]), "+f"(c[3])
        : "r"(a[0]), "r"(a[1]), "r"(a[2]), "r"(a[3]), "r"(b[0]), "r"(b[1]));
}
// exp2 on the FMA pipe
__device__ __forceinline__ float exp2p(float x) {
    float t = x + 12582912.0f;
    int   n = __float_as_int(t) - 0x4B400000;
    float f = x - (t - 12582912.0f);
    float r = 1.3333558e-3f;
    r = fmaf(r, f, 9.6181291e-3f);
    r = fmaf(r, f, 5.5504109e-2f);
    r = fmaf(r, f, 2.4022651e-1f);
    r = fmaf(r, f, 6.9314718e-1f);
    r = fmaf(r, f, 1.0f);
    return __int_as_float(__float_as_int(r) + (n << 23));
}

// ---------------------------------------------------------------------------
// Weight transpose: g_wt[z][n][k] = W_z[k][n]
// ---------------------------------------------------------------------------
__global__ void wt_kernel(const float* __restrict__ Wq, const float* __restrict__ Wk,
                          const float* __restrict__ Wv, const float* __restrict__ Wo) {
    __shared__ float t[32][33];
    const int z = blockIdx.z;
    const float* W = (z == 0) ? Wq : (z == 1) ? Wk : (z == 2) ? Wv : Wo;
    float* T = g_wt + z * kD * kD;
    const int k0 = blockIdx.x * 32, n0 = blockIdx.y * 32;
    #pragma unroll
    for (int i = 0; i < 4; i++)
        t[threadIdx.y + i * 8][threadIdx.x] =
            W[(k0 + threadIdx.y + i * 8) * kD + n0 + threadIdx.x];
    __syncthreads();
    #pragma unroll
    for (int i = 0; i < 4; i++)
        T[(n0 + threadIdx.y + i * 8) * kD + k0 + threadIdx.x] =
            t[threadIdx.x][threadIdx.y + i * 8];
}

// ---------------------------------------------------------------------------
// mma.sync tf32 GEMM (unchanged from R7)
// ---------------------------------------------------------------------------
__device__ __forceinline__ void gemm_mma(const float* __restrict__ A,
                                         const float* __restrict__ Wt,
                                         const float* __restrict__ bias,
                                         float* __restrict__ O,
                                         int row0, int col0, float scale,
                                         bool gather, bool headt) {
    extern __shared__ float sm[];
    const int tid  = threadIdx.x;
    const int wid  = tid >> 5;
    const int lane = tid & 31;
    const int wm   = (wid >> 2) * 64;
    const int wn   = (wid & 3) * 32;

    float c[4][4][4];
    #pragma unroll
    for (int mt = 0; mt < 4; mt++)
        #pragma unroll
        for (int nt = 0; nt < 4; nt++)
            #pragma unroll
            for (int e = 0; e < 4; e++) c[mt][nt][e] = 0.f;

    float4 va[4], vb[4];
    auto gload = [&](int k0) {
        #pragma unroll
        for (int t = 0; t < 4; t++) {
            const int idx = tid + t * 256;
            const int r = idx >> 3, c4 = idx & 7;
            if (gather) {
                int rg = row0 + r;
                int bb = rg >> 10, l = rg & 1023;
                int k = k0 + c4 * 4;
                int h = k >> 6, hd = k & 63;
                va[t] = *reinterpret_cast<const float4*>(
                    &g_ctx[(((bb * kH + h) * kL + l) * kHD) + hd]);
            } else {
                va[t] = *reinterpret_cast<const float4*>(&A[(row0 + r) * kD + k0 + c4 * 4]);
            }
            vb[t] = *reinterpret_cast<const float4*>(&Wt[(col0 + r) * kD + k0 + c4 * 4]);
        }
    };
    auto sts = [&](int buf) {
        float* As = sm + buf * kGemmBufFloats;
        float* Bs = sm + (2 + buf) * kGemmBufFloats;
        #pragma unroll
        for (int t = 0; t < 4; t++) {
            const int idx = tid + t * 256;
            const int r = idx >> 3, c4 = idx & 7;
            float4 wa, wb;
            wa.x = tf32f(va[t].x); wa.y = tf32f(va[t].y);
            wa.z = tf32f(va[t].z); wa.w = tf32f(va[t].w);
            wb.x = tf32f(vb[t].x); wb.y = tf32f(vb[t].y);
            wb.z = tf32f(vb[t].z); wb.w = tf32f(vb[t].w);
            *reinterpret_cast<float4*>(&As[r * 36 + c4 * 4]) = wa;
            *reinterpret_cast<float4*>(&Bs[r * 36 + c4 * 4]) = wb;
        }
    };
    auto compute = [&](int buf) {
        const float* As = sm + buf * kGemmBufFloats;
        const float* Bs = sm + (2 + buf) * kGemmBufFloats;
        const int r0 = wm + (lane >> 2);
        const int n0 = wn + (lane >> 2);
        #pragma unroll
        for (int k8 = 0; k8 < 4; k8++) {
            const int kc = k8 * 8 + (lane & 3);
            uint32_t a[4][4], b[4][2];
            #pragma unroll
            for (int mt = 0; mt < 4; mt++) {
                a[mt][0] = __float_as_uint(As[(r0 + mt * 16) * 36 + kc]);
                a[mt][1] = __float_as_uint(As[(r0 + mt * 16 + 8) * 36 + kc]);
                a[mt][2] = __float_as_uint(As[(r0 + mt * 16) * 36 + kc + 4]);
                a[mt][3] = __float_as_uint(As[(r0 + mt * 16 + 8) * 36 + kc + 4]);
            }
            #pragma unroll
            for (int nt = 0; nt < 4; nt++) {
                b[nt][0] = __float_as_uint(Bs[(n0 + nt * 8) * 36 + kc]);
                b[nt][1] = __float_as_uint(Bs[(n0 + nt * 8) * 36 + kc + 4]);
            }
            #pragma unroll
            for (int mt = 0; mt < 4; mt++)
                #pragma unroll
                for (int nt = 0; nt < 4; nt++)
                    mma_tf32(c[mt][nt], a[mt], b[nt]);
        }
    };

    gload(0);
    sts(0);
    __syncthreads();
    for (int it = 0; it < 16; it++) {
        if (it < 15) gload((it + 1) * 32);
        compute(it & 1);
        if (it < 15) {
            __syncthreads();
            sts((it + 1) & 1);
            __syncthreads();
        }
    }

    #pragma unroll
    for (int mt = 0; mt < 4; mt++) {
        #pragma unroll
        for (int nt = 0; nt < 4; nt++) {
            const int row = row0 + wm + mt * 16 + (lane >> 2);
            const int col = col0 + wn + nt * 8 + 2 * (lane & 3);
            const float b0 = bias[col], b1 = bias[col + 1];
            #pragma unroll
            for (int half = 0; half < 2; half++) {
                const int r = row + half * 8;
                float2 v;
                v.x = (c[mt][nt][half * 2 + 0] + b0) * scale;
                v.y = (c[mt][nt][half * 2 + 1] + b1) * scale;
                if (headt) {
                    const int bb = r >> 10, l = r & 1023;
                    const int h = col >> 6, hd = col & 63;
                    *reinterpret_cast<float2*>(
                        &O[(((bb * kH + h) * kL + l) * kHD) + hd]) = v;
                } else {
                    *reinterpret_cast<float2*>(&O[r * kD + col]) = v;
                }
            }
        }
    }
}

__global__ void __launch_bounds__(256, 2)
qkv_tc_kernel(const float* __restrict__ xq, const float* __restrict__ xk,
              const float* __restrict__ xv,
              const float* __restrict__ bq, const float* __restrict__ bk,
              const float* __restrict__ bv) {
    const int z = blockIdx.z;
    const float* X    = (z == 0) ? xq : (z == 1) ? xk : xv;
    const float* bias = (z == 0) ? bq : (z == 1) ? bk : bv;
    float* O          = (z == 0) ? g_q : (z == 1) ? g_k : g_v;
    const float scale = (z == 0) ? kQScale : 1.0f;
    gemm_mma(X, g_wt + z * kD * kD, bias, O,
             blockIdx.y * 128, blockIdx.x * 128, scale, false, true);
}

__global__ void __launch_bounds__(256, 2)
proj_tc_kernel(const float* __restrict__ bo, float* __restrict__ out) {
    gemm_mma(nullptr, g_wt + 3 * kD * kD, bo, out,
             blockIdx.y * 128, blockIdx.x * 128, 1.0f, true, false);
}

// ---------------------------------------------------------------------------
// FUSED attention: one CTA per (bh, 64 query rows). grid(16, 64), 256 thr,
// 96 KB smem -> 2 CTA/SM. Per causal m-tile (128 wide):
//   E-MMA: panel[l][63-lloc+mloc] = q.E (fp16 smem, E stays in L2)
//   QK MMA + exp2(qk + panel) ; pass1: rowsums only; pass2: normalize,
//   write attn from fragments, P@V accumulate via staged tf32 chunks.
// ---------------------------------------------------------------------------
__global__ void __launch_bounds__(256, 2)
fused_attn_kernel(const float* __restrict__ relE, float* __restrict__ attn) {
    extern __shared__ float sm[];
    float*  Qs    = sm;                                  // [64][68]
    float*  big   = sm + kQsFloats;                      // Eseg/K/V^T
    float*  pan_f = sm + kQsFloats + kBigFloats;         // panel region
    __half* panel = reinterpret_cast<__half*>(pan_f);    // [64][200] halves
    float*  Pchunk= pan_f;                               // [64][68] alias
    float*  rs    = sm + kQsFloats + kBigFloats + kPanFloats;  // [128]
    float*  rsinv = rs + 128;                            // [64]

    const int lt  = 15 - blockIdx.x;         // heavy CTAs first
    const int bh  = blockIdx.y;
    const int l0  = lt * 64;
    const int nmt = (l0 >> 7) + 1;

    const int tid  = threadIdx.x;
    const int wid  = tid >> 5;
    const int lane = tid & 31;
    const int wm   = (wid >> 1) * 16;        // 4 M-warps x 16 rows
    const int wN   = wid & 1;                // 2 N-warps
    const int qrow = lane >> 2;
    const int qk   = lane & 3;
    const int rowA = wm + qrow, rowB = rowA + 8;
    const int lA = l0 + rowA, lB = l0 + rowB;

    // Q tile -> tf32 smem
    #pragma unroll
    for (int t = 0; t < 4; t++) {
        int idx = tid + t * 256;
        int r = idx >> 4, d4 = idx & 15;
        float4 q4 = *reinterpret_cast<const float4*>(
            &g_q[(bh * kL + l0 + r) * kHD + d4 * 4]);
        float4 w;
        w.x = tf32f(q4.x); w.y = tf32f(q4.y); w.z = tf32f(q4.z); w.w = tf32f(q4.w);
        *reinterpret_cast<float4*>(&Qs[r * 68 + d4 * 4]) = w;
    }
    // zero-fill upper attn columns
    {
        const int c0 = nmt * 128;
        if (c0 < kL) {
            float4* dst = reinterpret_cast<float4*>(attn + (size_t)(bh * kL + l0) * kL);
            const int ncol4 = (kL - c0) >> 2;
            const float4 z4 = make_float4(0.f, 0.f, 0.f, 0.f);
            for (int idx = tid; idx < 64 * ncol4; idx += 256) {
                int r = idx / ncol4, c = idx % ncol4;
                dst[r * (kL >> 2) + (c0 >> 2) + c] = z4;
            }
        }
    }

    float rs0 = 0.f, rs1 = 0.f;
    float rv0 = 0.f, rv1 = 0.f;
    float acc[4][4];
    #pragma unroll
    for (int nt = 0; nt < 4; nt++)
        #pragma unroll
        for (int e = 0; e < 4; e++) acc[nt][e] = 0.f;

    for (int pass = 0; pass < 2; pass++) {
        for (int mt = 0; mt < nmt; mt++) {
            const int m0 = mt * 128;
            const int rbase = 960 - l0 + m0;
            __syncthreads();                   // big + panel free
            // ---- Eseg load (192 rows, clamp >=1024 to zero) ----
            #pragma unroll
            for (int t = 0; t < 12; t++) {
                int idx = tid + t * 256;
                int j = idx >> 4, d4 = idx & 15;
                int er = rbase + j;
                float4 e4 = make_float4(0.f, 0.f, 0.f, 0.f);
                if (er < 1024)
                    e4 = *reinterpret_cast<const float4*>(&relE[er * kHD + d4 * 4]);
                float4 w;
                w.x = tf32f(e4.x); w.y = tf32f(e4.y); w.z = tf32f(e4.z); w.w = tf32f(e4.w);
                *reinterpret_cast<float4*>(&big[j * 68 + d4 * 4]) = w;
            }
            __syncthreads();
            // ---- E-MMA -> panel (fp16) ----
            {
                float ce[12][4];
                #pragma unroll
                for (int nt = 0; nt < 12; nt++)
                    #pragma unroll
                    for (int e = 0; e < 4; e++) ce[nt][e] = 0.f;
                #pragma unroll
                for (int k8 = 0; k8 < 8; k8++) {
                    const int kc = k8 * 8 + qk;
                    uint32_t a[4];
                    a[0] = __float_as_uint(Qs[rowA * 68 + kc]);
                    a[1] = __float_as_uint(Qs[rowB * 68 + kc]);
                    a[2] = __float_as_uint(Qs[rowA * 68 + kc + 4]);
                    a[3] = __float_as_uint(Qs[rowB * 68 + kc + 4]);
                    #pragma unroll
                    for (int nt = 0; nt < 12; nt++) {
                        const int n = wN * 96 + nt * 8 + qrow;
                        uint32_t b[2];
                        b[0] = __float_as_uint(big[n * 68 + kc]);
                        b[1] = __float_as_uint(big[n * 68 + kc + 4]);
                        mma_tf32(ce[nt], a, b);
                    }
                }
                #pragma unroll
                for (int nt = 0; nt < 12; nt++) {
                    const int col = wN * 96 + nt * 8 + 2 * qk;
                    *reinterpret_cast<__half2*>(&panel[rowA * 200 + col]) =
                        __floats2half2_rn(ce[nt][0], ce[nt][1]);
                    *reinterpret_cast<__half2*>(&panel[rowB * 200 + col]) =
                        __floats2half2_rn(ce[nt][2], ce[nt][3]);
                }
            }
            __syncthreads();                   // panel ready, big free
            // ---- K tile load ----
            #pragma unroll
            for (int t = 0; t < 8; t++) {
                int idx = tid + t * 256;
                int r = idx >> 4, d4 = idx & 15;
                float4 k4 = *reinterpret_cast<const float4*>(
                    &g_k[(bh * kL + m0 + r) * kHD + d4 * 4]);
                float4 w;
                w.x = tf32f(k4.x); w.y = tf32f(k4.y); w.z = tf32f(k4.z); w.w = tf32f(k4.w);
                *reinterpret_cast<float4*>(&big[r * 68 + d4 * 4]) = w;
            }
            __syncthreads();
            // ---- QK MMA ----
            float c[8][4];
            #pragma unroll
            for (int nt = 0; nt < 8; nt++)
                #pragma unroll
                for (int e = 0; e < 4; e++) c[nt][e] = 0.f;
            #pragma unroll
            for (int k8 = 0; k8 < 8; k8++) {
                const int kc = k8 * 8 + qk;
                uint32_t a[4];
                a[0] = __float_as_uint(Qs[rowA * 68 + kc]);
                a[1] = __float_as_uint(Qs[rowB * 68 + kc]);
                a[2] = __float_as_uint(Qs[rowA * 68 + kc + 4]);
                a[3] = __float_as_uint(Qs[rowB * 68 + kc + 4]);
                #pragma unroll
                for (int nt = 0; nt < 8; nt++) {
                    const int n = wN * 64 + nt * 8 + qrow;
                    uint32_t b[2];
                    b[0] = __float_as_uint(big[n * 68 + kc]);
                    b[1] = __float_as_uint(big[n * 68 + kc + 4]);
                    mma_tf32(c[nt], a, b);
                }
            }
            __syncthreads();                   // all QK reads of big done
            // ---- V^T load (pass 2 only) ----
            if (pass == 1) {
                #pragma unroll
                for (int t = 0; t < 8; t++) {
                    int idx = tid + t * 256;
                    int m = idx >> 4, d4 = idx & 15;
                    float4 v4 = *reinterpret_cast<const float4*>(
                        &g_v[(bh * kL + m0 + m) * kHD + d4 * 4]);
                    big[(d4 * 4 + 0) * 132 + m] = tf32f(v4.x);
                    big[(d4 * 4 + 1) * 132 + m] = tf32f(v4.y);
                    big[(d4 * 4 + 2) * 132 + m] = tf32f(v4.z);
                    big[(d4 * 4 + 3) * 132 + m] = tf32f(v4.w);
                }
            }
            // ---- exp2(qk + qe) with causal mask ----
            #pragma unroll
            for (int nt = 0; nt < 8; nt++) {
                #pragma unroll
                for (int e = 0; e < 2; e++) {
                    const int col = wN * 64 + nt * 8 + 2 * qk + e;
                    const int m = m0 + col;
                    float vA = 0.f, vB = 0.f;
                    if (m <= lA)
                        vA = exp2p(c[nt][e] +
                                   __half2float(panel[rowA * 200 + (63 - rowA + col)]));
                    if (m <= lB)
                        vB = exp2p(c[nt][2 + e] +
                                   __half2float(panel[rowB * 200 + (63 - rowB + col)]));
                    if (pass == 0) { rs0 += vA; rs1 += vB; }
                    c[nt][e] = vA;
                    c[nt][2 + e] = vB;
                }
            }
            if (pass == 1) {
                // normalize + write attn directly from fragments
                #pragma unroll
                for (int nt = 0; nt < 8; nt++) {
                    const int col = wN * 64 + nt * 8 + 2 * qk;
                    const int m = m0 + col;
                    float2 vA = make_float2(c[nt][0] * rv0, c[nt][1] * rv0);
                    float2 vB = make_float2(c[nt][2] * rv1, c[nt][3] * rv1);
                    *reinterpret_cast<float2*>(&attn[(size_t)(bh * kL + lA) * kL + m]) = vA;
                    *reinterpret_cast<float2*>(&attn[(size_t)(bh * kL + lB) * kL + m]) = vB;
                    c[nt][0] = vA.x; c[nt][1] = vA.y;
                    c[nt][2] = vB.x; c[nt][3] = vB.y;
                }
                __syncthreads();               // V^T ready; panel free (exp done)
                // ---- P @ V in two 64-wide k-chunks ----
                #pragma unroll
                for (int h = 0; h < 2; h++) {
                    if (wN == h) {
                        #pragma unroll
                        for (int nt = 0; nt < 8; nt++) {
                            const int cl = nt * 8 + 2 * qk;
                            float2 pA = make_float2(tf32f(c[nt][0]), tf32f(c[nt][1]));
                            float2 pB = make_float2(tf32f(c[nt][2]), tf32f(c[nt][3]));
                            *reinterpret_cast<float2*>(&Pchunk[rowA * 68 + cl]) = pA;
                            *reinterpret_cast<float2*>(&Pchunk[rowB * 68 + cl]) = pB;
                        }
                    }
                    __syncthreads();
                    #pragma unroll
                    for (int k8 = 0; k8 < 8; k8++) {
                        const int kc = k8 * 8 + qk;
                        uint32_t a[4];
                        a[0] = __float_as_uint(Pchunk[rowA * 68 + kc]);
                        a[1] = __float_as_uint(Pchunk[rowB * 68 + kc]);
                        a[2] = __float_as_uint(Pchunk[rowA * 68 + kc + 4]);
                        a[3] = __float_as_uint(Pchunk[rowB * 68 + kc + 4]);
                        #pragma unroll
                        for (int nt = 0; nt < 4; nt++) {
                            const int n = wN * 32 + nt * 8 + qrow;
                            uint32_t b[2];
                            b[0] = __float_as_uint(big[n * 132 + h * 64 + kc]);
                            b[1] = __float_as_uint(big[n * 132 + h * 64 + kc + 4]);
                            mma_tf32(acc[nt], a, b);
                        }
                    }
                    __syncthreads();
                }
            }
        } // mt
        if (pass == 0) {
            rs0 += __shfl_xor_sync(0xffffffffu, rs0, 1);
            rs0 += __shfl_xor_sync(0xffffffffu, rs0, 2);
            rs1 += __shfl_xor_sync(0xffffffffu, rs1, 1);
            rs1 += __shfl_xor_sync(0xffffffffu, rs1, 2);
            if (qk == 0) {
                rs[rowA * 2 + wN] = rs0;
                rs[rowB * 2 + wN] = rs1;
            }
            __syncthreads();
            if (tid < 64) rsinv[tid] = 1.f / (rs[tid * 2] + rs[tid * 2 + 1]);
            __syncthreads();
            rv0 = rsinv[rowA];
            rv1 = rsinv[rowB];
        }
    } // pass

    // ctx epilogue (P was normalized -> ctx already normalized)
    #pragma unroll
    for (int nt = 0; nt < 4; nt++) {
        const int d = wN * 32 + nt * 8 + 2 * qk;
        *reinterpret_cast<float2*>(&g_ctx[(size_t)(bh * kL + lA) * kHD + d]) =
            make_float2(acc[nt][0], acc[nt][1]);
        *reinterpret_cast<float2*>(&g_ctx[(size_t)(bh * kL + lB) * kHD + d]) =
            make_float2(acc[nt][2], acc[nt][3]);
    }
}

// ---------------------------------------------------------------------------
extern "C" void kernel_launch(void* const* d_in, const int* in_sizes, int n_in,
                              void* d_out, int out_size) {
    const float* xq   = (const float*)d_in[0];
    const float* xk   = (const float*)d_in[1];
    const float* xv   = (const float*)d_in[2];
    // d_in[3] = mask (unused: causal mask applied analytically)
    const float* Wq   = (const float*)d_in[4];
    const float* bq   = (const float*)d_in[5];
    const float* Wk   = (const float*)d_in[6];
    const float* bk   = (const float*)d_in[7];
    const float* Wv   = (const float*)d_in[8];
    const float* bv   = (const float*)d_in[9];
    const float* Wo   = (const float*)d_in[10];
    const float* bo   = (const float*)d_in[11];
    const float* relE = (const float*)d_in[12];

    float* out = (float*)d_out;
    float* attn;
    if (out_size >= kOutElems + kAttnElems) {
        attn = out + kOutElems;
    } else {
        cudaGetSymbolAddress((void**)&attn, g_fb);   // never expected in practice
    }

    cudaFuncSetAttribute(fused_attn_kernel, cudaFuncAttributeMaxDynamicSharedMemorySize,
                         kFusedSmemBytes);
    cudaFuncSetAttribute(qkv_tc_kernel, cudaFuncAttributeMaxDynamicSharedMemorySize,
                         kGemmSmemBytes);
    cudaFuncSetAttribute(proj_tc_kernel, cudaFuncAttributeMaxDynamicSharedMemorySize,
                         kGemmSmemBytes);

    wt_kernel<<<dim3(16, 16, 4), dim3(32, 8)>>>(Wq, Wk, Wv, Wo);
    qkv_tc_kernel<<<dim3(kD / 128, (kB * kL) / 128, 3), 256, kGemmSmemBytes>>>(
        xq, xk, xv, bq, bk, bv);
    fused_attn_kernel<<<dim3(16, kBH), 256, kFusedSmemBytes>>>(relE, attn);
    proj_tc_kernel<<<dim3(kD / 128, (kB * kL) / 128), 256, kGemmSmemBytes>>>(bo, out);
}

// round 9
// speedup vs baseline: 1.2100x; 1.2100x over previous
#include <cuda_runtime.h>
#include <cuda_fp16.h>
#include <cstdint>

// ---------------------------------------------------------------------------
// Problem constants
// ---------------------------------------------------------------------------
namespace {
constexpr int kB  = 8;
constexpr int kL  = 1024;
constexpr int kD  = 512;
constexpr int kH  = 8;
constexpr int kHD = 64;
constexpr int kBH = kB * kH;                 // 64
constexpr int kOutElems  = kB * kL * kD;     // 4,194,304
constexpr int kAttnElems = kBH * kL * kL;    // 67,108,864

// mma.sync GEMM smem: 2 buffers x (As[128][36] + Bs[128][36]) floats
constexpr int kGemmBufFloats  = 128 * 36;                   // 4,608
constexpr int kGemmSmemBytes  = 4 * kGemmBufFloats * 4;     // 73,728 B

constexpr int kQeSmemBytes    = 2 * 128 * 68 * 4;           // 69,632 B
constexpr int kScoreSmemBytes = 2 * 128 * 68 * 4;           // 69,632 B (stage+rs alias)
constexpr int kPvSmemFloats   = 128 * 132 + 64 * 132 + 128;
constexpr int kPvSmemBytes    = kPvSmemFloats * 4;          // 101,888 B

// fold softmax 1/sqrt(64) and log2(e) into q so score does exp2(qk+qe)
constexpr float kQScale = 0.125f * 1.4426950408889634f;
}

// Scratch (device globals; no allocations allowed)
__device__ float  g_q[kBH * kL * kHD];
__device__ float  g_k[kBH * kL * kHD];
__device__ float  g_v[kBH * kL * kHD];
__device__ float  g_ctx[kBH * kL * kHD];
__device__ __half g_qe[kBH * kL * kL];       // QE skew, fp16 (134 MB)
__device__ __half g_ph[kBH * kL * kL];       // unnormalized p, fp16 (134 MB)
__device__ float  g_rspart[kBH * kL * 8];    // per-(row, m-tile) rowsum partials
__device__ float  g_wt[4 * kD * kD];         // W^T for q,k,v,o
__device__ float  g_fb[kAttnElems];          // fallback attn sink (never expected)

// ---------------------------------------------------------------------------
// Helpers
// ---------------------------------------------------------------------------
__device__ __forceinline__ uint32_t f2tf32(float x) {
    uint32_t r;
    asm("cvt.rna.tf32.f32 %0, %1;" : "=r"(r) : "f"(x));
    return r;
}
__device__ __forceinline__ float tf32f(float x) {
    return __uint_as_float(f2tf32(x));
}
__device__ __forceinline__ void mma_tf32(float* c, const uint32_t* a, const uint32_t* b) {
    asm volatile(
        "mma.sync.aligned.m16n8k8.row.col.f32.tf32.tf32.f32 "
        "{%0,%1,%2,%3}, {%4,%5,%6,%7}, {%8,%9}, {%0,%1,%2,%3};"
        : "+f"(c[0]), "+f"(c[1]), "+f"(c[2]), "+f"(c[3])
        : "r"(a[0]), "r"(a[1]), "r"(a[2]), "r"(a[3]), "r"(b[0]), "r"(b[1]));
}
// exp2 on the FMA pipe: magic round + degree-5 Taylor for 2^f, f in [-.5,.5]
__device__ __forceinline__ float exp2p(float x) {
    float t = x + 12582912.0f;
    int   n = __float_as_int(t) - 0x4B400000;
    float f = x - (t - 12582912.0f);
    float r = 1.3333558e-3f;
    r = fmaf(r, f, 9.6181291e-3f);
    r = fmaf(r, f, 5.5504109e-2f);
    r = fmaf(r, f, 2.4022651e-1f);
    r = fmaf(r, f, 6.9314718e-1f);
    r = fmaf(r, f, 1.0f);
    return __int_as_float(__float_as_int(r) + (n << 23));
}

// ---------------------------------------------------------------------------
// Weight transpose: g_wt[z][n][k] = W_z[k][n]
// ---------------------------------------------------------------------------
__global__ void wt_kernel(const float* __restrict__ Wq, const float* __restrict__ Wk,
                          const float* __restrict__ Wv, const float* __restrict__ Wo) {
    __shared__ float t[32][33];
    const int z = blockIdx.z;
    const float* W = (z == 0) ? Wq : (z == 1) ? Wk : (z == 2) ? Wv : Wo;
    float* T = g_wt + z * kD * kD;
    const int k0 = blockIdx.x * 32, n0 = blockIdx.y * 32;
    #pragma unroll
    for (int i = 0; i < 4; i++)
        t[threadIdx.y + i * 8][threadIdx.x] =
            W[(k0 + threadIdx.y + i * 8) * kD + n0 + threadIdx.x];
    __syncthreads();
    #pragma unroll
    for (int i = 0; i < 4; i++)
        T[(n0 + threadIdx.y + i * 8) * kD + k0 + threadIdx.x] =
            t[threadIdx.x][threadIdx.y + i * 8];
}

// ---------------------------------------------------------------------------
// mma.sync tf32 GEMM: C[128x128] = A[128x512] @ Wt[128x512]^T + bias, scaled.
// ---------------------------------------------------------------------------
__device__ __forceinline__ void gemm_mma(const float* __restrict__ A,
                                         const float* __restrict__ Wt,
                                         const float* __restrict__ bias,
                                         float* __restrict__ O,
                                         int row0, int col0, float scale,
                                         bool gather, bool headt) {
    extern __shared__ float sm[];
    const int tid  = threadIdx.x;
    const int wid  = tid >> 5;
    const int lane = tid & 31;
    const int wm   = (wid >> 2) * 64;
    const int wn   = (wid & 3) * 32;

    float c[4][4][4];
    #pragma unroll
    for (int mt = 0; mt < 4; mt++)
        #pragma unroll
        for (int nt = 0; nt < 4; nt++)
            #pragma unroll
            for (int e = 0; e < 4; e++) c[mt][nt][e] = 0.f;

    float4 va[4], vb[4];
    auto gload = [&](int k0) {
        #pragma unroll
        for (int t = 0; t < 4; t++) {
            const int idx = tid + t * 256;
            const int r = idx >> 3, c4 = idx & 7;
            if (gather) {
                int rg = row0 + r;
                int bb = rg >> 10, l = rg & 1023;
                int k = k0 + c4 * 4;
                int h = k >> 6, hd = k & 63;
                va[t] = *reinterpret_cast<const float4*>(
                    &g_ctx[(((bb * kH + h) * kL + l) * kHD) + hd]);
            } else {
                va[t] = *reinterpret_cast<const float4*>(&A[(row0 + r) * kD + k0 + c4 * 4]);
            }
            vb[t] = *reinterpret_cast<const float4*>(&Wt[(col0 + r) * kD + k0 + c4 * 4]);
        }
    };
    auto sts = [&](int buf) {
        float* As = sm + buf * kGemmBufFloats;
        float* Bs = sm + (2 + buf) * kGemmBufFloats;
        #pragma unroll
        for (int t = 0; t < 4; t++) {
            const int idx = tid + t * 256;
            const int r = idx >> 3, c4 = idx & 7;
            float4 wa, wb;
            wa.x = tf32f(va[t].x); wa.y = tf32f(va[t].y);
            wa.z = tf32f(va[t].z); wa.w = tf32f(va[t].w);
            wb.x = tf32f(vb[t].x); wb.y = tf32f(vb[t].y);
            wb.z = tf32f(vb[t].z); wb.w = tf32f(vb[t].w);
            *reinterpret_cast<float4*>(&As[r * 36 + c4 * 4]) = wa;
            *reinterpret_cast<float4*>(&Bs[r * 36 + c4 * 4]) = wb;
        }
    };
    auto compute = [&](int buf) {
        const float* As = sm + buf * kGemmBufFloats;
        const float* Bs = sm + (2 + buf) * kGemmBufFloats;
        const int r0 = wm + (lane >> 2);
        const int n0 = wn + (lane >> 2);
        #pragma unroll
        for (int k8 = 0; k8 < 4; k8++) {
            const int kc = k8 * 8 + (lane & 3);
            uint32_t a[4][4], b[4][2];
            #pragma unroll
            for (int mt = 0; mt < 4; mt++) {
                a[mt][0] = __float_as_uint(As[(r0 + mt * 16) * 36 + kc]);
                a[mt][1] = __float_as_uint(As[(r0 + mt * 16 + 8) * 36 + kc]);
                a[mt][2] = __float_as_uint(As[(r0 + mt * 16) * 36 + kc + 4]);
                a[mt][3] = __float_as_uint(As[(r0 + mt * 16 + 8) * 36 + kc + 4]);
            }
            #pragma unroll
            for (int nt = 0; nt < 4; nt++) {
                b[nt][0] = __float_as_uint(Bs[(n0 + nt * 8) * 36 + kc]);
                b[nt][1] = __float_as_uint(Bs[(n0 + nt * 8) * 36 + kc + 4]);
            }
            #pragma unroll
            for (int mt = 0; mt < 4; mt++)
                #pragma unroll
                for (int nt = 0; nt < 4; nt++)
                    mma_tf32(c[mt][nt], a[mt], b[nt]);
        }
    };

    gload(0);
    sts(0);
    __syncthreads();
    for (int it = 0; it < 16; it++) {
        if (it < 15) gload((it + 1) * 32);
        compute(it & 1);
        if (it < 15) {
            __syncthreads();
            sts((it + 1) & 1);
            __syncthreads();
        }
    }

    #pragma unroll
    for (int mt = 0; mt < 4; mt++) {
        #pragma unroll
        for (int nt = 0; nt < 4; nt++) {
            const int row = row0 + wm + mt * 16 + (lane >> 2);
            const int col = col0 + wn + nt * 8 + 2 * (lane & 3);
            const float b0 = bias[col], b1 = bias[col + 1];
            #pragma unroll
            for (int half = 0; half < 2; half++) {
                const int r = row + half * 8;
                float2 v;
                v.x = (c[mt][nt][half * 2 + 0] + b0) * scale;
                v.y = (c[mt][nt][half * 2 + 1] + b1) * scale;
                if (headt) {
                    const int bb = r >> 10, l = r & 1023;
                    const int h = col >> 6, hd = col & 63;
                    *reinterpret_cast<float2*>(
                        &O[(((bb * kH + h) * kL + l) * kHD) + hd]) = v;
                } else {
                    *reinterpret_cast<float2*>(&O[r * kD + col]) = v;
                }
            }
        }
    }
}

__global__ void __launch_bounds__(256, 2)
qkv_tc_kernel(const float* __restrict__ xq, const float* __restrict__ xk,
              const float* __restrict__ xv,
              const float* __restrict__ bq, const float* __restrict__ bk,
              const float* __restrict__ bv) {
    const int z = blockIdx.z;
    const float* X    = (z == 0) ? xq : (z == 1) ? xk : xv;
    const float* bias = (z == 0) ? bq : (z == 1) ? bk : bv;
    float* O          = (z == 0) ? g_q : (z == 1) ? g_k : g_v;
    const float scale = (z == 0) ? kQScale : 1.0f;
    gemm_mma(X, g_wt + z * kD * kD, bias, O,
             blockIdx.y * 128, blockIdx.x * 128, scale, false, true);
}

__global__ void __launch_bounds__(256, 2)
proj_tc_kernel(const float* __restrict__ bo, float* __restrict__ out) {
    gemm_mma(nullptr, g_wt + 3 * kD * kD, bo, out,
             blockIdx.y * 128, blockIdx.x * 128, 1.0f, true, false);
}

// ---------------------------------------------------------------------------
// QE kernel (mma.sync): QE[row, r] = q[row,:] . E[r,:], K=64 one-shot.
// fp16 output. 128x128 tiles, 8 warps. Causal-band tile skip.
// ---------------------------------------------------------------------------
__global__ void __launch_bounds__(256, 2)
qe_mma_kernel(const float* __restrict__ relE) {
    const int r0    = blockIdx.x * 128;
    const int row0  = blockIdx.y * 128;
    const int l0loc = row0 & (kL - 1);
    if (l0loc + r0 < 769) return;

    extern __shared__ float sm[];
    float* Qs = sm;                  // [128][68] tf32 bits
    float* Es = sm + 128 * 68;       // [128][68]

    const int tid  = threadIdx.x;
    const int wid  = tid >> 5;
    const int lane = tid & 31;
    const int wm   = (wid >> 2) * 64;
    const int wn   = (wid & 3) * 32;

    #pragma unroll
    for (int t = 0; t < 8; t++) {
        int idx = tid + t * 256;
        int r = idx >> 4, d4 = idx & 15;
        float4 q4 = *reinterpret_cast<const float4*>(&g_q[(row0 + r) * kHD + d4 * 4]);
        float4 e4 = *reinterpret_cast<const float4*>(&relE[(r0 + r) * kHD + d4 * 4]);
        float4 wq, we;
        wq.x = tf32f(q4.x); wq.y = tf32f(q4.y); wq.z = tf32f(q4.z); wq.w = tf32f(q4.w);
        we.x = tf32f(e4.x); we.y = tf32f(e4.y); we.z = tf32f(e4.z); we.w = tf32f(e4.w);
        *reinterpret_cast<float4*>(&Qs[r * 68 + d4 * 4]) = wq;
        *reinterpret_cast<float4*>(&Es[r * 68 + d4 * 4]) = we;
    }
    __syncthreads();

    float c[4][4][4];
    #pragma unroll
    for (int mt = 0; mt < 4; mt++)
        #pragma unroll
        for (int nt = 0; nt < 4; nt++)
            #pragma unroll
            for (int e = 0; e < 4; e++) c[mt][nt][e] = 0.f;

    const int r0a = wm + (lane >> 2);
    const int n0b = wn + (lane >> 2);
    #pragma unroll
    for (int k8 = 0; k8 < 8; k8++) {
        const int kc = k8 * 8 + (lane & 3);
        uint32_t a[4][4], b[4][2];
        #pragma unroll
        for (int mt = 0; mt < 4; mt++) {
            a[mt][0] = __float_as_uint(Qs[(r0a + mt * 16) * 68 + kc]);
            a[mt][1] = __float_as_uint(Qs[(r0a + mt * 16 + 8) * 68 + kc]);
            a[mt][2] = __float_as_uint(Qs[(r0a + mt * 16) * 68 + kc + 4]);
            a[mt][3] = __float_as_uint(Qs[(r0a + mt * 16 + 8) * 68 + kc + 4]);
        }
        #pragma unroll
        for (int nt = 0; nt < 4; nt++) {
            b[nt][0] = __float_as_uint(Es[(n0b + nt * 8) * 68 + kc]);
            b[nt][1] = __float_as_uint(Es[(n0b + nt * 8) * 68 + kc + 4]);
        }
        #pragma unroll
        for (int mt = 0; mt < 4; mt++)
            #pragma unroll
            for (int nt = 0; nt < 4; nt++)
                mma_tf32(c[mt][nt], a[mt], b[nt]);
    }

    #pragma unroll
    for (int mt = 0; mt < 4; mt++)
        #pragma unroll
        for (int nt = 0; nt < 4; nt++) {
            const int row = row0 + wm + mt * 16 + (lane >> 2);
            const int col = r0 + wn + nt * 8 + 2 * (lane & 3);
            #pragma unroll
            for (int half = 0; half < 2; half++) {
                __half2 v = __floats2half2_rn(c[mt][nt][half * 2],
                                              c[mt][nt][half * 2 + 1]);
                *reinterpret_cast<__half2*>(
                    &g_qe[(size_t)(row + half * 8) * kL + col]) = v;
            }
        }
}

// ---------------------------------------------------------------------------
// score kernel: one CTA per causal 128x128 tile. grid(36, 64).
// p = exp2(qk + qe_fp16) -> fp16 into g_ph; rowsum partials -> g_rspart.
// ---------------------------------------------------------------------------
__global__ void __launch_bounds__(256, 2)
score_mma_kernel() {
    extern __shared__ float sm[];
    float* Qs = sm;                  // [128][68]
    float* Ks = sm + 128 * 68;       // [128][68]

    const int ti = blockIdx.x;
    int lt = 0;
    #pragma unroll
    for (int t = 1; t < 8; t++)
        if (ti >= (t * (t + 1)) / 2) lt = t;
    const int mt_t = ti - (lt * (lt + 1)) / 2;
    const int bh = blockIdx.y;
    const int l0 = lt * 128;
    const int m0 = mt_t * 128;

    const int tid  = threadIdx.x;
    const int wid  = tid >> 5;
    const int lane = tid & 31;
    const int wm   = (wid >> 2) * 64;
    const int wn   = (wid & 3) * 32;

    #pragma unroll
    for (int t = 0; t < 8; t++) {
        int idx = tid + t * 256;
        int r = idx >> 4, d4 = idx & 15;
        float4 q4 = *reinterpret_cast<const float4*>(
            &g_q[(bh * kL + l0 + r) * kHD + d4 * 4]);
        float4 k4 = *reinterpret_cast<const float4*>(
            &g_k[(bh * kL + m0 + r) * kHD + d4 * 4]);
        float4 wq, wk;
        wq.x = tf32f(q4.x); wq.y = tf32f(q4.y); wq.z = tf32f(q4.z); wq.w = tf32f(q4.w);
        wk.x = tf32f(k4.x); wk.y = tf32f(k4.y); wk.z = tf32f(k4.z); wk.w = tf32f(k4.w);
        *reinterpret_cast<float4*>(&Qs[r * 68 + d4 * 4]) = wq;
        *reinterpret_cast<float4*>(&Ks[r * 68 + d4 * 4]) = wk;
    }
    __syncthreads();

    float c[4][4][4];
    #pragma unroll
    for (int mt = 0; mt < 4; mt++)
        #pragma unroll
        for (int nt = 0; nt < 4; nt++)
            #pragma unroll
            for (int e = 0; e < 4; e++) c[mt][nt][e] = 0.f;

    const int r0a = wm + (lane >> 2);
    const int n0b = wn + (lane >> 2);
    #pragma unroll
    for (int k8 = 0; k8 < 8; k8++) {
        const int kc = k8 * 8 + (lane & 3);
        uint32_t a[4][4], b[4][2];
        #pragma unroll
        for (int mt = 0; mt < 4; mt++) {
            a[mt][0] = __float_as_uint(Qs[(r0a + mt * 16) * 68 + kc]);
            a[mt][1] = __float_as_uint(Qs[(r0a + mt * 16 + 8) * 68 + kc]);
            a[mt][2] = __float_as_uint(Qs[(r0a + mt * 16) * 68 + kc + 4]);
            a[mt][3] = __float_as_uint(Qs[(r0a + mt * 16 + 8) * 68 + kc + 4]);
        }
        #pragma unroll
        for (int nt = 0; nt < 4; nt++) {
            b[nt][0] = __float_as_uint(Ks[(n0b + nt * 8) * 68 + kc]);
            b[nt][1] = __float_as_uint(Ks[(n0b + nt * 8) * 68 + kc + 4]);
        }
        #pragma unroll
        for (int mt = 0; mt < 4; mt++)
            #pragma unroll
            for (int nt = 0; nt < 4; nt++)
                mma_tf32(c[mt][nt], a[mt], b[nt]);
    }
    __syncthreads();                 // Qs/Ks dead; alias as fp16 stage + rs

    __half* stageH = reinterpret_cast<__half*>(sm);   // [128][136] halves
    float*  rs     = sm + (128 * 136 * 2) / 4;        // [128][4] floats

    #pragma unroll
    for (int mt = 0; mt < 4; mt++) {
        #pragma unroll
        for (int half = 0; half < 2; half++) {
            const int row = wm + mt * 16 + (lane >> 2) + half * 8;
            const int l   = l0 + row;
            const __half* qe_row = g_qe + (size_t)(bh * kL + l) * kL + (1023 - l);
            float rp = 0.f;
            #pragma unroll
            for (int nt = 0; nt < 4; nt++) {
                const int col = wn + nt * 8 + 2 * (lane & 3);
                const int m   = m0 + col;
                float v0 = 0.f, v1 = 0.f;
                if (m <= l)
                    v0 = exp2p(c[mt][nt][half * 2 + 0] +
                               __half2float(__ldg(qe_row + m)));
                if (m + 1 <= l)
                    v1 = exp2p(c[mt][nt][half * 2 + 1] +
                               __half2float(__ldg(qe_row + m + 1)));
                *reinterpret_cast<__half2*>(&stageH[row * 136 + col]) =
                    __floats2half2_rn(v0, v1);
                rp += v0 + v1;
            }
            rp += __shfl_xor_sync(0xffffffffu, rp, 1);
            rp += __shfl_xor_sync(0xffffffffu, rp, 2);
            if ((lane & 3) == 0) rs[row * 4 + (wid & 3)] = rp;
        }
    }
    __syncthreads();

    if (tid < 128) {
        float s = rs[tid * 4] + rs[tid * 4 + 1] + rs[tid * 4 + 2] + rs[tid * 4 + 3];
        g_rspart[(size_t)(bh * kL + l0 + tid) * 8 + mt_t] = s;
    }

    // coalesced fp16 tile store (16B chunks)
    __half* dst = g_ph + (size_t)(bh * kL + l0) * kL + m0;
    #pragma unroll
    for (int t = 0; t < 8; t++) {
        int idx = tid + t * 256;
        int r = idx >> 4, c8 = idx & 15;
        uint4 v = *reinterpret_cast<const uint4*>(&stageH[r * 136 + c8 * 8]);
        *reinterpret_cast<uint4*>(dst + (size_t)r * kL + c8 * 8) = v;
    }
}

// ---------------------------------------------------------------------------
// pv kernel: one CTA per (bh, 128 rows). grid(8,64), 2 CTA/SM.
// Reads fp16 p, normalizes, writes fp32 attn, ctx += p_norm @ V (tf32 MMA).
// ---------------------------------------------------------------------------
__global__ void __launch_bounds__(256, 2)
pv_mma_kernel(float* __restrict__ attn) {
    extern __shared__ float sm[];
    float* As    = sm;                       // [128][132] p tile (tf32 bits)
    float* vst   = As + 128 * 132;           // [64][132] V^T (tf32 bits)
    float* rsinv = vst + 64 * 132;           // [128]

    const int lt  = 7 - blockIdx.x;          // heavy CTAs first
    const int bh  = blockIdx.y;
    const int l0  = lt * 128;
    const int tid = threadIdx.x;
    const int wid  = tid >> 5;
    const int lane = tid & 31;
    const int wm   = (wid >> 2) * 64;
    const int wn   = (wid & 3) * 16;

    if (tid < 128) {
        float s = 0.f;
        for (int mt = 0; mt <= lt; mt++)
            s += g_rspart[(size_t)(bh * kL + l0 + tid) * 8 + mt];
        rsinv[tid] = 1.f / s;
    }

    // zero-fill strictly-upper attn tiles for these rows
    {
        const int c0 = (lt + 1) * 128;
        float4* dst = reinterpret_cast<float4*>(attn + (size_t)(bh * kL + l0) * kL);
        const int ncol4 = (kL - c0) / 4;
        for (int idx = tid; idx < 128 * ncol4; idx += 256) {
            int r = idx / ncol4, c = idx % ncol4;
            dst[r * (kL / 4) + c0 / 4 + c] = make_float4(0.f, 0.f, 0.f, 0.f);
        }
    }
    __syncthreads();

    float c[4][2][4];
    #pragma unroll
    for (int mt = 0; mt < 4; mt++)
        #pragma unroll
        for (int nt = 0; nt < 2; nt++)
            #pragma unroll
            for (int e = 0; e < 4; e++) c[mt][nt][e] = 0.f;

    for (int mtile = 0; mtile <= lt; mtile++) {
        // V tile -> transposed tf32 smem [d][m]
        #pragma unroll
        for (int t = 0; t < 8; t++) {
            int idx = tid + t * 256;
            int m = idx >> 4, d4 = idx & 15;
            float4 v4 = *reinterpret_cast<const float4*>(
                &g_v[(bh * kL + mtile * 128 + m) * kHD + d4 * 4]);
            vst[(d4 * 4 + 0) * 132 + m] = tf32f(v4.x);
            vst[(d4 * 4 + 1) * 132 + m] = tf32f(v4.y);
            vst[(d4 * 4 + 2) * 132 + m] = tf32f(v4.z);
            vst[(d4 * 4 + 3) * 132 + m] = tf32f(v4.w);
        }
        // p tile: load fp16, normalize, write fp32 attn, stage tf32
        {
            const __half* src = g_ph + (size_t)(bh * kL + l0) * kL + mtile * 128;
            float4* pa = reinterpret_cast<float4*>(
                attn + (size_t)(bh * kL + l0) * kL + mtile * 128);
            #pragma unroll
            for (int t = 0; t < 8; t++) {
                int idx = tid + t * 256;
                int r = idx >> 4, c8 = idx & 15;
                uint4 raw = *reinterpret_cast<const uint4*>(
                    src + (size_t)r * kL + c8 * 8);
                const float inv = rsinv[r];
                float2 f0 = __half22float2(*reinterpret_cast<__half2*>(&raw.x));
                float2 f1 = __half22float2(*reinterpret_cast<__half2*>(&raw.y));
                float2 f2 = __half22float2(*reinterpret_cast<__half2*>(&raw.z));
                float2 f3 = __half22float2(*reinterpret_cast<__half2*>(&raw.w));
                float4 o0 = make_float4(f0.x * inv, f0.y * inv, f1.x * inv, f1.y * inv);
                float4 o1 = make_float4(f2.x * inv, f2.y * inv, f3.x * inv, f3.y * inv);
                pa[r * (kL / 4) + c8 * 2 + 0] = o0;
                pa[r * (kL / 4) + c8 * 2 + 1] = o1;
                float* st = &As[r * 132 + c8 * 8];
                st[0] = tf32f(o0.x); st[1] = tf32f(o0.y);
                st[2] = tf32f(o0.z); st[3] = tf32f(o0.w);
                st[4] = tf32f(o1.x); st[5] = tf32f(o1.y);
                st[6] = tf32f(o1.z); st[7] = tf32f(o1.w);
            }
        }
        __syncthreads();

        const int r0a = wm + (lane >> 2);
        const int n0b = wn + (lane >> 2);
        #pragma unroll
        for (int k8 = 0; k8 < 16; k8++) {
            const int kc = k8 * 8 + (lane & 3);
            uint32_t a[4][4], b[2][2];
            #pragma unroll
            for (int mt = 0; mt < 4; mt++) {
                a[mt][0] = __float_as_uint(As[(r0a + mt * 16) * 132 + kc]);
                a[mt][1] = __float_as_uint(As[(r0a + mt * 16 + 8) * 132 + kc]);
                a[mt][2] = __float_as_uint(As[(r0a + mt * 16) * 132 + kc + 4]);
                a[mt][3] = __float_as_uint(As[(r0a + mt * 16 + 8) * 132 + kc + 4]);
            }
            #pragma unroll
            for (int nt = 0; nt < 2; nt++) {
                b[nt][0] = __float_as_uint(vst[(n0b + nt * 8) * 132 + kc]);
                b[nt][1] = __float_as_uint(vst[(n0b + nt * 8) * 132 + kc + 4]);
            }
            #pragma unroll
            for (int mt = 0; mt < 4; mt++)
                #pragma unroll
                for (int nt = 0; nt < 2; nt++)
                    mma_tf32(c[mt][nt], a[mt], b[nt]);
        }
        __syncthreads();
    }

    // ctx epilogue
    #pragma unroll
    for (int mt = 0; mt < 4; mt++)
        #pragma unroll
        for (int nt = 0; nt < 2; nt++) {
            const int d = wn + nt * 8 + 2 * (lane & 3);
            #pragma unroll
            for (int half = 0; half < 2; half++) {
                const int row = l0 + wm + mt * 16 + (lane >> 2) + half * 8;
                float2 v = make_float2(c[mt][nt][half * 2], c[mt][nt][half * 2 + 1]);
                *reinterpret_cast<float2*>(
                    &g_ctx[(size_t)(bh * kL + row) * kHD + d]) = v;
            }
        }
}

// ---------------------------------------------------------------------------
extern "C" void kernel_launch(void* const* d_in, const int* in_sizes, int n_in,
                              void* d_out, int out_size) {
    const float* xq   = (const float*)d_in[0];
    const float* xk   = (const float*)d_in[1];
    const float* xv   = (const float*)d_in[2];
    // d_in[3] = mask (unused: causal mask applied analytically)
    const float* Wq   = (const float*)d_in[4];
    const float* bq   = (const float*)d_in[5];
    const float* Wk   = (const float*)d_in[6];
    const float* bk   = (const float*)d_in[7];
    const float* Wv   = (const float*)d_in[8];
    const float* bv   = (const float*)d_in[9];
    const float* Wo   = (const float*)d_in[10];
    const float* bo   = (const float*)d_in[11];
    const float* relE = (const float*)d_in[12];

    float* out = (float*)d_out;
    float* attn;
    if (out_size >= kOutElems + kAttnElems) {
        attn = out + kOutElems;
    } else {
        cudaGetSymbolAddress((void**)&attn, g_fb);   // never expected in practice
    }

    cudaFuncSetAttribute(qe_mma_kernel, cudaFuncAttributeMaxDynamicSharedMemorySize,
                         kQeSmemBytes);
    cudaFuncSetAttribute(score_mma_kernel, cudaFuncAttributeMaxDynamicSharedMemorySize,
                         kScoreSmemBytes);
    cudaFuncSetAttribute(pv_mma_kernel, cudaFuncAttributeMaxDynamicSharedMemorySize,
                         kPvSmemBytes);
    cudaFuncSetAttribute(qkv_tc_kernel, cudaFuncAttributeMaxDynamicSharedMemorySize,
                         kGemmSmemBytes);
    cudaFuncSetAttribute(proj_tc_kernel, cudaFuncAttributeMaxDynamicSharedMemorySize,
                         kGemmSmemBytes);

    wt_kernel<<<dim3(16, 16, 4), dim3(32, 8)>>>(Wq, Wk, Wv, Wo);
    qkv_tc_kernel<<<dim3(kD / 128, (kB * kL) / 128, 3), 256, kGemmSmemBytes>>>(
        xq, xk, xv, bq, bk, bv);
    qe_mma_kernel<<<dim3(kL / 128, (kBH * kL) / 128), 256, kQeSmemBytes>>>(relE);
    score_mma_kernel<<<dim3(36, kBH), 256, kScoreSmemBytes>>>();
    pv_mma_kernel<<<dim3(8, kBH), 256, kPvSmemBytes>>>(attn);
    proj_tc_kernel<<<dim3(kD / 128, (kB * kL) / 128), 256, kGemmSmemBytes>>>(bo, out);
}

// round 10
// speedup vs baseline: 1.2212x; 1.0092x over previous
#include <cuda_runtime.h>
#include <cuda_fp16.h>
#include <cstdint>

// ---------------------------------------------------------------------------
// Problem constants
// ---------------------------------------------------------------------------
namespace {
constexpr int kB  = 8;
constexpr int kL  = 1024;
constexpr int kD  = 512;
constexpr int kH  = 8;
constexpr int kHD = 64;
constexpr int kBH = kB * kH;                 // 64
constexpr int kOutElems  = kB * kL * kD;     // 4,194,304
constexpr int kAttnElems = kBH * kL * kL;    // 67,108,864

// mma.sync GEMM smem: 2 buffers x (As[128][36] + Bs[128][36]) floats
constexpr int kGemmBufFloats  = 128 * 36;                   // 4,608
constexpr int kGemmSmemBytes  = 4 * kGemmBufFloats * 4;     // 73,728 B

constexpr int kQeSmemBytes    = 2 * 128 * 68 * 4;           // 69,632 B
constexpr int kScoreSmemBytes = 2 * 128 * 68 * 4;           // 69,632 B (stage+rs alias)
constexpr int kPvSmemFloats   = 128 * 132 + 64 * 132 + 128;
constexpr int kPvSmemBytes    = kPvSmemFloats * 4;          // 101,888 B

// fold softmax 1/sqrt(64) and log2(e) into q so score does exp2(qk+qe)
constexpr float kQScale = 0.125f * 1.4426950408889634f;
}

// Scratch (device globals; no allocations allowed)
__device__ float  g_q[kBH * kL * kHD];
__device__ float  g_k[kBH * kL * kHD];
__device__ float  g_v[kBH * kL * kHD];
__device__ float  g_ctx[kBH * kL * kHD];
__device__ __half g_qe[kBH * kL * kL];       // QE skew, fp16 (134 MB)
__device__ __half g_ph[kBH * kL * kL];       // unnormalized p, fp16 (134 MB)
__device__ float  g_rspart[kBH * kL * 8];    // per-(row, m-tile) rowsum partials
__device__ float  g_wt[4 * kD * kD];         // W^T for q,k,v,o
__device__ float  g_fb[kAttnElems];          // fallback attn sink (never expected)

// ---------------------------------------------------------------------------
// Helpers
// ---------------------------------------------------------------------------
__device__ __forceinline__ uint32_t f2tf32(float x) {
    uint32_t r;
    asm("cvt.rna.tf32.f32 %0, %1;" : "=r"(r) : "f"(x));
    return r;
}
__device__ __forceinline__ float tf32f(float x) {
    return __uint_as_float(f2tf32(x));
}
__device__ __forceinline__ void mma_tf32(float* c, const uint32_t* a, const uint32_t* b) {
    asm volatile(
        "mma.sync.aligned.m16n8k8.row.col.f32.tf32.tf32.f32 "
        "{%0,%1,%2,%3}, {%4,%5,%6,%7}, {%8,%9}, {%0,%1,%2,%3};"
        : "+f"(c[0]), "+f"(c[1]), "+f"(c[2]), "+f"(c[3])
        : "r"(a[0]), "r"(a[1]), "r"(a[2]), "r"(a[3]), "r"(b[0]), "r"(b[1]));
}
// exp2 on the FMA pipe: magic round + degree-5 Taylor for 2^f, f in [-.5,.5]
__device__ __forceinline__ float exp2p(float x) {
    float t = x + 12582912.0f;
    int   n = __float_as_int(t) - 0x4B400000;
    float f = x - (t - 12582912.0f);
    float r = 1.3333558e-3f;
    r = fmaf(r, f, 9.6181291e-3f);
    r = fmaf(r, f, 5.5504109e-2f);
    r = fmaf(r, f, 2.4022651e-1f);
    r = fmaf(r, f, 6.9314718e-1f);
    r = fmaf(r, f, 1.0f);
    return __int_as_float(__float_as_int(r) + (n << 23));
}

// ---------------------------------------------------------------------------
// Weight transpose: g_wt[z][n][k] = W_z[k][n]
// ---------------------------------------------------------------------------
__global__ void wt_kernel(const float* __restrict__ Wq, const float* __restrict__ Wk,
                          const float* __restrict__ Wv, const float* __restrict__ Wo) {
    __shared__ float t[32][33];
    const int z = blockIdx.z;
    const float* W = (z == 0) ? Wq : (z == 1) ? Wk : (z == 2) ? Wv : Wo;
    float* T = g_wt + z * kD * kD;
    const int k0 = blockIdx.x * 32, n0 = blockIdx.y * 32;
    #pragma unroll
    for (int i = 0; i < 4; i++)
        t[threadIdx.y + i * 8][threadIdx.x] =
            W[(k0 + threadIdx.y + i * 8) * kD + n0 + threadIdx.x];
    __syncthreads();
    #pragma unroll
    for (int i = 0; i < 4; i++)
        T[(n0 + threadIdx.y + i * 8) * kD + k0 + threadIdx.x] =
            t[threadIdx.x][threadIdx.y + i * 8];
}

// ---------------------------------------------------------------------------
// mma.sync tf32 GEMM: C[128x128] = A[128x512] @ Wt[128x512]^T + bias, scaled.
// ---------------------------------------------------------------------------
__device__ __forceinline__ void gemm_mma(const float* __restrict__ A,
                                         const float* __restrict__ Wt,
                                         const float* __restrict__ bias,
                                         float* __restrict__ O,
                                         int row0, int col0, float scale,
                                         bool gather, bool headt) {
    extern __shared__ float sm[];
    const int tid  = threadIdx.x;
    const int wid  = tid >> 5;
    const int lane = tid & 31;
    const int wm   = (wid >> 2) * 64;
    const int wn   = (wid & 3) * 32;

    float c[4][4][4];
    #pragma unroll
    for (int mt = 0; mt < 4; mt++)
        #pragma unroll
        for (int nt = 0; nt < 4; nt++)
            #pragma unroll
            for (int e = 0; e < 4; e++) c[mt][nt][e] = 0.f;

    float4 va[4], vb[4];
    auto gload = [&](int k0) {
        #pragma unroll
        for (int t = 0; t < 4; t++) {
            const int idx = tid + t * 256;
            const int r = idx >> 3, c4 = idx & 7;
            if (gather) {
                int rg = row0 + r;
                int bb = rg >> 10, l = rg & 1023;
                int k = k0 + c4 * 4;
                int h = k >> 6, hd = k & 63;
                va[t] = *reinterpret_cast<const float4*>(
                    &g_ctx[(((bb * kH + h) * kL + l) * kHD) + hd]);
            } else {
                va[t] = *reinterpret_cast<const float4*>(&A[(row0 + r) * kD + k0 + c4 * 4]);
            }
            vb[t] = *reinterpret_cast<const float4*>(&Wt[(col0 + r) * kD + k0 + c4 * 4]);
        }
    };
    auto sts = [&](int buf) {
        float* As = sm + buf * kGemmBufFloats;
        float* Bs = sm + (2 + buf) * kGemmBufFloats;
        #pragma unroll
        for (int t = 0; t < 4; t++) {
            const int idx = tid + t * 256;
            const int r = idx >> 3, c4 = idx & 7;
            float4 wa, wb;
            wa.x = tf32f(va[t].x); wa.y = tf32f(va[t].y);
            wa.z = tf32f(va[t].z); wa.w = tf32f(va[t].w);
            wb.x = tf32f(vb[t].x); wb.y = tf32f(vb[t].y);
            wb.z = tf32f(vb[t].z); wb.w = tf32f(vb[t].w);
            *reinterpret_cast<float4*>(&As[r * 36 + c4 * 4]) = wa;
            *reinterpret_cast<float4*>(&Bs[r * 36 + c4 * 4]) = wb;
        }
    };
    auto compute = [&](int buf) {
        const float* As = sm + buf * kGemmBufFloats;
        const float* Bs = sm + (2 + buf) * kGemmBufFloats;
        const int r0 = wm + (lane >> 2);
        const int n0 = wn + (lane >> 2);
        #pragma unroll
        for (int k8 = 0; k8 < 4; k8++) {
            const int kc = k8 * 8 + (lane & 3);
            uint32_t a[4][4], b[4][2];
            #pragma unroll
            for (int mt = 0; mt < 4; mt++) {
                a[mt][0] = __float_as_uint(As[(r0 + mt * 16) * 36 + kc]);
                a[mt][1] = __float_as_uint(As[(r0 + mt * 16 + 8) * 36 + kc]);
                a[mt][2] = __float_as_uint(As[(r0 + mt * 16) * 36 + kc + 4]);
                a[mt][3] = __float_as_uint(As[(r0 + mt * 16 + 8) * 36 + kc + 4]);
            }
            #pragma unroll
            for (int nt = 0; nt < 4; nt++) {
                b[nt][0] = __float_as_uint(Bs[(n0 + nt * 8) * 36 + kc]);
                b[nt][1] = __float_as_uint(Bs[(n0 + nt * 8) * 36 + kc + 4]);
            }
            #pragma unroll
            for (int mt = 0; mt < 4; mt++)
                #pragma unroll
                for (int nt = 0; nt < 4; nt++)
                    mma_tf32(c[mt][nt], a[mt], b[nt]);
        }
    };

    gload(0);
    sts(0);
    __syncthreads();
    for (int it = 0; it < 16; it++) {
        if (it < 15) gload((it + 1) * 32);
        compute(it & 1);
        if (it < 15) {
            __syncthreads();
            sts((it + 1) & 1);
            __syncthreads();
        }
    }

    #pragma unroll
    for (int mt = 0; mt < 4; mt++) {
        #pragma unroll
        for (int nt = 0; nt < 4; nt++) {
            const int row = row0 + wm + mt * 16 + (lane >> 2);
            const int col = col0 + wn + nt * 8 + 2 * (lane & 3);
            const float b0 = bias[col], b1 = bias[col + 1];
            #pragma unroll
            for (int half = 0; half < 2; half++) {
                const int r = row + half * 8;
                float2 v;
                v.x = (c[mt][nt][half * 2 + 0] + b0) * scale;
                v.y = (c[mt][nt][half * 2 + 1] + b1) * scale;
                if (headt) {
                    const int bb = r >> 10, l = r & 1023;
                    const int h = col >> 6, hd = col & 63;
                    *reinterpret_cast<float2*>(
                        &O[(((bb * kH + h) * kL + l) * kHD) + hd]) = v;
                } else {
                    __stcs(reinterpret_cast<float2*>(&O[r * kD + col]), v);
                }
            }
        }
    }
}

__global__ void __launch_bounds__(256, 2)
qkv_tc_kernel(const float* __restrict__ xq, const float* __restrict__ xk,
              const float* __restrict__ xv,
              const float* __restrict__ bq, const float* __restrict__ bk,
              const float* __restrict__ bv) {
    const int z = blockIdx.z;
    const float* X    = (z == 0) ? xq : (z == 1) ? xk : xv;
    const float* bias = (z == 0) ? bq : (z == 1) ? bk : bv;
    float* O          = (z == 0) ? g_q : (z == 1) ? g_k : g_v;
    const float scale = (z == 0) ? kQScale : 1.0f;
    gemm_mma(X, g_wt + z * kD * kD, bias, O,
             blockIdx.y * 128, blockIdx.x * 128, scale, false, true);
}

__global__ void __launch_bounds__(256, 2)
proj_tc_kernel(const float* __restrict__ bo, float* __restrict__ out) {
    gemm_mma(nullptr, g_wt + 3 * kD * kD, bo, out,
             blockIdx.y * 128, blockIdx.x * 128, 1.0f, true, false);
}

// ---------------------------------------------------------------------------
// QE kernel (mma.sync): QE[row, r] = q[row,:] . E[r,:], K=64 one-shot.
// fp16 output. 128x128 tiles, 8 warps. Causal-band tile skip.
// ---------------------------------------------------------------------------
__global__ void __launch_bounds__(256, 2)
qe_mma_kernel(const float* __restrict__ relE) {
    const int r0    = blockIdx.x * 128;
    const int row0  = blockIdx.y * 128;
    const int l0loc = row0 & (kL - 1);
    if (l0loc + r0 < 769) return;

    extern __shared__ float sm[];
    float* Qs = sm;                  // [128][68] tf32 bits
    float* Es = sm + 128 * 68;       // [128][68]

    const int tid  = threadIdx.x;
    const int wid  = tid >> 5;
    const int lane = tid & 31;
    const int wm   = (wid >> 2) * 64;
    const int wn   = (wid & 3) * 32;

    #pragma unroll
    for (int t = 0; t < 8; t++) {
        int idx = tid + t * 256;
        int r = idx >> 4, d4 = idx & 15;
        float4 q4 = *reinterpret_cast<const float4*>(&g_q[(row0 + r) * kHD + d4 * 4]);
        float4 e4 = *reinterpret_cast<const float4*>(&relE[(r0 + r) * kHD + d4 * 4]);
        float4 wq, we;
        wq.x = tf32f(q4.x); wq.y = tf32f(q4.y); wq.z = tf32f(q4.z); wq.w = tf32f(q4.w);
        we.x = tf32f(e4.x); we.y = tf32f(e4.y); we.z = tf32f(e4.z); we.w = tf32f(e4.w);
        *reinterpret_cast<float4*>(&Qs[r * 68 + d4 * 4]) = wq;
        *reinterpret_cast<float4*>(&Es[r * 68 + d4 * 4]) = we;
    }
    __syncthreads();

    float c[4][4][4];
    #pragma unroll
    for (int mt = 0; mt < 4; mt++)
        #pragma unroll
        for (int nt = 0; nt < 4; nt++)
            #pragma unroll
            for (int e = 0; e < 4; e++) c[mt][nt][e] = 0.f;

    const int r0a = wm + (lane >> 2);
    const int n0b = wn + (lane >> 2);
    #pragma unroll
    for (int k8 = 0; k8 < 8; k8++) {
        const int kc = k8 * 8 + (lane & 3);
        uint32_t a[4][4], b[4][2];
        #pragma unroll
        for (int mt = 0; mt < 4; mt++) {
            a[mt][0] = __float_as_uint(Qs[(r0a + mt * 16) * 68 + kc]);
            a[mt][1] = __float_as_uint(Qs[(r0a + mt * 16 + 8) * 68 + kc]);
            a[mt][2] = __float_as_uint(Qs[(r0a + mt * 16) * 68 + kc + 4]);
            a[mt][3] = __float_as_uint(Qs[(r0a + mt * 16 + 8) * 68 + kc + 4]);
        }
        #pragma unroll
        for (int nt = 0; nt < 4; nt++) {
            b[nt][0] = __float_as_uint(Es[(n0b + nt * 8) * 68 + kc]);
            b[nt][1] = __float_as_uint(Es[(n0b + nt * 8) * 68 + kc + 4]);
        }
        #pragma unroll
        for (int mt = 0; mt < 4; mt++)
            #pragma unroll
            for (int nt = 0; nt < 4; nt++)
                mma_tf32(c[mt][nt], a[mt], b[nt]);
    }

    #pragma unroll
    for (int mt = 0; mt < 4; mt++)
        #pragma unroll
        for (int nt = 0; nt < 4; nt++) {
            const int row = row0 + wm + mt * 16 + (lane >> 2);
            const int col = r0 + wn + nt * 8 + 2 * (lane & 3);
            #pragma unroll
            for (int half = 0; half < 2; half++) {
                __half2 v = __floats2half2_rn(c[mt][nt][half * 2],
                                              c[mt][nt][half * 2 + 1]);
                *reinterpret_cast<__half2*>(
                    &g_qe[(size_t)(row + half * 8) * kL + col]) = v;
            }
        }
}

// ---------------------------------------------------------------------------
// score kernel: one CTA per causal 128x128 tile. grid(36, 64).
// p = exp2(qk + qe_fp16) -> fp16 into g_ph; rowsum partials -> g_rspart.
// CTAs ti<28 also zero-fill one strictly-upper 128x128 attn tile (overlapped,
// fire-and-forget __stcs stores).
// ---------------------------------------------------------------------------
__global__ void __launch_bounds__(256, 2)
score_mma_kernel(float* __restrict__ attn) {
    extern __shared__ float sm[];
    float* Qs = sm;                  // [128][68]
    float* Ks = sm + 128 * 68;       // [128][68]

    const int ti = blockIdx.x;
    int lt = 0;
    #pragma unroll
    for (int t = 1; t < 8; t++)
        if (ti >= (t * (t + 1)) / 2) lt = t;
    const int mt_t = ti - (lt * (lt + 1)) / 2;
    const int bh = blockIdx.y;
    const int l0 = lt * 128;
    const int m0 = mt_t * 128;

    const int tid  = threadIdx.x;
    const int wid  = tid >> 5;
    const int lane = tid & 31;
    const int wm   = (wid >> 2) * 64;
    const int wn   = (wid & 3) * 32;

    // ---- overlapped zero-fill of one strictly-upper attn tile ----
    if (ti < 28) {
        int j = ti, zlt = 0;
        while (j >= 7 - zlt) { j -= 7 - zlt; zlt++; }
        const int zmt = zlt + 1 + j;
        float4* zdst = reinterpret_cast<float4*>(
            attn + (size_t)(bh * kL + zlt * 128) * kL + zmt * 128);
        const float4 z4 = make_float4(0.f, 0.f, 0.f, 0.f);
        #pragma unroll
        for (int t = 0; t < 16; t++) {
            int idx = tid + t * 256;
            int r = idx >> 5, c4 = idx & 31;
            __stcs(&zdst[r * (kL / 4) + c4], z4);
        }
    }

    #pragma unroll
    for (int t = 0; t < 8; t++) {
        int idx = tid + t * 256;
        int r = idx >> 4, d4 = idx & 15;
        float4 q4 = *reinterpret_cast<const float4*>(
            &g_q[(bh * kL + l0 + r) * kHD + d4 * 4]);
        float4 k4 = *reinterpret_cast<const float4*>(
            &g_k[(bh * kL + m0 + r) * kHD + d4 * 4]);
        float4 wq, wk;
        wq.x = tf32f(q4.x); wq.y = tf32f(q4.y); wq.z = tf32f(q4.z); wq.w = tf32f(q4.w);
        wk.x = tf32f(k4.x); wk.y = tf32f(k4.y); wk.z = tf32f(k4.z); wk.w = tf32f(k4.w);
        *reinterpret_cast<float4*>(&Qs[r * 68 + d4 * 4]) = wq;
        *reinterpret_cast<float4*>(&Ks[r * 68 + d4 * 4]) = wk;
    }
    __syncthreads();

    float c[4][4][4];
    #pragma unroll
    for (int mt = 0; mt < 4; mt++)
        #pragma unroll
        for (int nt = 0; nt < 4; nt++)
            #pragma unroll
            for (int e = 0; e < 4; e++) c[mt][nt][e] = 0.f;

    const int r0a = wm + (lane >> 2);
    const int n0b = wn + (lane >> 2);
    #pragma unroll
    for (int k8 = 0; k8 < 8; k8++) {
        const int kc = k8 * 8 + (lane & 3);
        uint32_t a[4][4], b[4][2];
        #pragma unroll
        for (int mt = 0; mt < 4; mt++) {
            a[mt][0] = __float_as_uint(Qs[(r0a + mt * 16) * 68 + kc]);
            a[mt][1] = __float_as_uint(Qs[(r0a + mt * 16 + 8) * 68 + kc]);
            a[mt][2] = __float_as_uint(Qs[(r0a + mt * 16) * 68 + kc + 4]);
            a[mt][3] = __float_as_uint(Qs[(r0a + mt * 16 + 8) * 68 + kc + 4]);
        }
        #pragma unroll
        for (int nt = 0; nt < 4; nt++) {
            b[nt][0] = __float_as_uint(Ks[(n0b + nt * 8) * 68 + kc]);
            b[nt][1] = __float_as_uint(Ks[(n0b + nt * 8) * 68 + kc + 4]);
        }
        #pragma unroll
        for (int mt = 0; mt < 4; mt++)
            #pragma unroll
            for (int nt = 0; nt < 4; nt++)
                mma_tf32(c[mt][nt], a[mt], b[nt]);
    }
    __syncthreads();                 // Qs/Ks dead; alias as fp16 stage + rs

    __half* stageH = reinterpret_cast<__half*>(sm);   // [128][136] halves
    float*  rs     = sm + (128 * 136 * 2) / 4;        // [128][4] floats

    #pragma unroll
    for (int mt = 0; mt < 4; mt++) {
        #pragma unroll
        for (int half = 0; half < 2; half++) {
            const int row = wm + mt * 16 + (lane >> 2) + half * 8;
            const int l   = l0 + row;
            const __half* qe_row = g_qe + (size_t)(bh * kL + l) * kL + (1023 - l);
            float rp = 0.f;
            #pragma unroll
            for (int nt = 0; nt < 4; nt++) {
                const int col = wn + nt * 8 + 2 * (lane & 3);
                const int m   = m0 + col;
                float v0 = 0.f, v1 = 0.f;
                if (m <= l)
                    v0 = exp2p(c[mt][nt][half * 2 + 0] +
                               __half2float(__ldcs(qe_row + m)));
                if (m + 1 <= l)
                    v1 = exp2p(c[mt][nt][half * 2 + 1] +
                               __half2float(__ldcs(qe_row + m + 1)));
                *reinterpret_cast<__half2*>(&stageH[row * 136 + col]) =
                    __floats2half2_rn(v0, v1);
                rp += v0 + v1;
            }
            rp += __shfl_xor_sync(0xffffffffu, rp, 1);
            rp += __shfl_xor_sync(0xffffffffu, rp, 2);
            if ((lane & 3) == 0) rs[row * 4 + (wid & 3)] = rp;
        }
    }
    __syncthreads();

    if (tid < 128) {
        float s = rs[tid * 4] + rs[tid * 4 + 1] + rs[tid * 4 + 2] + rs[tid * 4 + 3];
        g_rspart[(size_t)(bh * kL + l0 + tid) * 8 + mt_t] = s;
    }

    // coalesced fp16 tile store (16B chunks)
    __half* dst = g_ph + (size_t)(bh * kL + l0) * kL + m0;
    #pragma unroll
    for (int t = 0; t < 8; t++) {
        int idx = tid + t * 256;
        int r = idx >> 4, c8 = idx & 15;
        uint4 v = *reinterpret_cast<const uint4*>(&stageH[r * 136 + c8 * 8]);
        *reinterpret_cast<uint4*>(dst + (size_t)r * kL + c8 * 8) = v;
    }
}

// ---------------------------------------------------------------------------
// pv kernel: one CTA per (bh, 128 rows). grid(8,64), 2 CTA/SM.
// Reads fp16 p (__ldcs), normalizes, writes fp32 attn (__stcs),
// ctx += p_norm @ V (tf32 MMA).
// ---------------------------------------------------------------------------
__global__ void __launch_bounds__(256, 2)
pv_mma_kernel(float* __restrict__ attn) {
    extern __shared__ float sm[];
    float* As    = sm;                       // [128][132] p tile (tf32 bits)
    float* vst   = As + 128 * 132;           // [64][132] V^T (tf32 bits)
    float* rsinv = vst + 64 * 132;           // [128]

    const int lt  = 7 - blockIdx.x;          // heavy CTAs first
    const int bh  = blockIdx.y;
    const int l0  = lt * 128;
    const int tid = threadIdx.x;
    const int wid  = tid >> 5;
    const int lane = tid & 31;
    const int wm   = (wid >> 2) * 64;
    const int wn   = (wid & 3) * 16;

    if (tid < 128) {
        float s = 0.f;
        for (int mt = 0; mt <= lt; mt++)
            s += g_rspart[(size_t)(bh * kL + l0 + tid) * 8 + mt];
        rsinv[tid] = 1.f / s;
    }
    __syncthreads();

    float c[4][2][4];
    #pragma unroll
    for (int mt = 0; mt < 4; mt++)
        #pragma unroll
        for (int nt = 0; nt < 2; nt++)
            #pragma unroll
            for (int e = 0; e < 4; e++) c[mt][nt][e] = 0.f;

    for (int mtile = 0; mtile <= lt; mtile++) {
        // V tile -> transposed tf32 smem [d][m]
        #pragma unroll
        for (int t = 0; t < 8; t++) {
            int idx = tid + t * 256;
            int m = idx >> 4, d4 = idx & 15;
            float4 v4 = *reinterpret_cast<const float4*>(
                &g_v[(bh * kL + mtile * 128 + m) * kHD + d4 * 4]);
            vst[(d4 * 4 + 0) * 132 + m] = tf32f(v4.x);
            vst[(d4 * 4 + 1) * 132 + m] = tf32f(v4.y);
            vst[(d4 * 4 + 2) * 132 + m] = tf32f(v4.z);
            vst[(d4 * 4 + 3) * 132 + m] = tf32f(v4.w);
        }
        // p tile: load fp16 (streaming), normalize, write fp32 attn (streaming),
        // stage tf32
        {
            const __half* src = g_ph + (size_t)(bh * kL + l0) * kL + mtile * 128;
            float4* pa = reinterpret_cast<float4*>(
                attn + (size_t)(bh * kL + l0) * kL + mtile * 128);
            #pragma unroll
            for (int t = 0; t < 8; t++) {
                int idx = tid + t * 256;
                int r = idx >> 4, c8 = idx & 15;
                uint4 raw = __ldcs(reinterpret_cast<const uint4*>(
                    src + (size_t)r * kL + c8 * 8));
                const float inv = rsinv[r];
                float2 f0 = __half22float2(*reinterpret_cast<__half2*>(&raw.x));
                float2 f1 = __half22float2(*reinterpret_cast<__half2*>(&raw.y));
                float2 f2 = __half22float2(*reinterpret_cast<__half2*>(&raw.z));
                float2 f3 = __half22float2(*reinterpret_cast<__half2*>(&raw.w));
                float4 o0 = make_float4(f0.x * inv, f0.y * inv, f1.x * inv, f1.y * inv);
                float4 o1 = make_float4(f2.x * inv, f2.y * inv, f3.x * inv, f3.y * inv);
                __stcs(&pa[r * (kL / 4) + c8 * 2 + 0], o0);
                __stcs(&pa[r * (kL / 4) + c8 * 2 + 1], o1);
                float* st = &As[r * 132 + c8 * 8];
                st[0] = tf32f(o0.x); st[1] = tf32f(o0.y);
                st[2] = tf32f(o0.z); st[3] = tf32f(o0.w);
                st[4] = tf32f(o1.x); st[5] = tf32f(o1.y);
                st[6] = tf32f(o1.z); st[7] = tf32f(o1.w);
            }
        }
        __syncthreads();

        const int r0a = wm + (lane >> 2);
        const int n0b = wn + (lane >> 2);
        #pragma unroll
        for (int k8 = 0; k8 < 16; k8++) {
            const int kc = k8 * 8 + (lane & 3);
            uint32_t a[4][4], b[2][2];
            #pragma unroll
            for (int mt = 0; mt < 4; mt++) {
                a[mt][0] = __float_as_uint(As[(r0a + mt * 16) * 132 + kc]);
                a[mt][1] = __float_as_uint(As[(r0a + mt * 16 + 8) * 132 + kc]);
                a[mt][2] = __float_as_uint(As[(r0a + mt * 16) * 132 + kc + 4]);
                a[mt][3] = __float_as_uint(As[(r0a + mt * 16 + 8) * 132 + kc + 4]);
            }
            #pragma unroll
            for (int nt = 0; nt < 2; nt++) {
                b[nt][0] = __float_as_uint(vst[(n0b + nt * 8) * 132 + kc]);
                b[nt][1] = __float_as_uint(vst[(n0b + nt * 8) * 132 + kc + 4]);
            }
            #pragma unroll
            for (int mt = 0; mt < 4; mt++)
                #pragma unroll
                for (int nt = 0; nt < 2; nt++)
                    mma_tf32(c[mt][nt], a[mt], b[nt]);
        }
        __syncthreads();
    }

    // ctx epilogue
    #pragma unroll
    for (int mt = 0; mt < 4; mt++)
        #pragma unroll
        for (int nt = 0; nt < 2; nt++) {
            const int d = wn + nt * 8 + 2 * (lane & 3);
            #pragma unroll
            for (int half = 0; half < 2; half++) {
                const int row = l0 + wm + mt * 16 + (lane >> 2) + half * 8;
                float2 v = make_float2(c[mt][nt][half * 2], c[mt][nt][half * 2 + 1]);
                *reinterpret_cast<float2*>(
                    &g_ctx[(size_t)(bh * kL + row) * kHD + d]) = v;
            }
        }
}

// ---------------------------------------------------------------------------
extern "C" void kernel_launch(void* const* d_in, const int* in_sizes, int n_in,
                              void* d_out, int out_size) {
    const float* xq   = (const float*)d_in[0];
    const float* xk   = (const float*)d_in[1];
    const float* xv   = (const float*)d_in[2];
    // d_in[3] = mask (unused: causal mask applied analytically)
    const float* Wq   = (const float*)d_in[4];
    const float* bq   = (const float*)d_in[5];
    const float* Wk   = (const float*)d_in[6];
    const float* bk   = (const float*)d_in[7];
    const float* Wv   = (const float*)d_in[8];
    const float* bv   = (const float*)d_in[9];
    const float* Wo   = (const float*)d_in[10];
    const float* bo   = (const float*)d_in[11];
    const float* relE = (const float*)d_in[12];

    float* out = (float*)d_out;
    float* attn;
    if (out_size >= kOutElems + kAttnElems) {
        attn = out + kOutElems;
    } else {
        cudaGetSymbolAddress((void**)&attn, g_fb);   // never expected in practice
    }

    cudaFuncSetAttribute(qe_mma_kernel, cudaFuncAttributeMaxDynamicSharedMemorySize,
                         kQeSmemBytes);
    cudaFuncSetAttribute(score_mma_kernel, cudaFuncAttributeMaxDynamicSharedMemorySize,
                         kScoreSmemBytes);
    cudaFuncSetAttribute(pv_mma_kernel, cudaFuncAttributeMaxDynamicSharedMemorySize,
                         kPvSmemBytes);
    cudaFuncSetAttribute(qkv_tc_kernel, cudaFuncAttributeMaxDynamicSharedMemorySize,
                         kGemmSmemBytes);
    cudaFuncSetAttribute(proj_tc_kernel, cudaFuncAttributeMaxDynamicSharedMemorySize,
                         kGemmSmemBytes);

    wt_kernel<<<dim3(16, 16, 4), dim3(32, 8)>>>(Wq, Wk, Wv, Wo);
    qkv_tc_kernel<<<dim3(kD / 128, (kB * kL) / 128, 3), 256, kGemmSmemBytes>>>(
        xq, xk, xv, bq, bk, bv);
    qe_mma_kernel<<<dim3(kL / 128, (kBH * kL) / 128), 256, kQeSmemBytes>>>(relE);
    score_mma_kernel<<<dim3(36, kBH), 256, kScoreSmemBytes>>>(attn);
    pv_mma_kernel<<<dim3(8, kBH), 256, kPvSmemBytes>>>(attn);
    proj_tc_kernel<<<dim3(kD / 128, (kB * kL) / 128), 256, kGemmSmemBytes>>>(bo, out);
}

// round 11
// speedup vs baseline: 1.2678x; 1.0382x over previous
#include <cuda_runtime.h>
#include <cuda_fp16.h>
#include <cstdint>

// ---------------------------------------------------------------------------
// Problem constants
// ---------------------------------------------------------------------------
namespace {
constexpr int kB  = 8;
constexpr int kL  = 1024;
constexpr int kD  = 512;
constexpr int kH  = 8;
constexpr int kHD = 64;
constexpr int kBH = kB * kH;                 // 64
constexpr int kOutElems  = kB * kL * kD;     // 4,194,304
constexpr int kAttnElems = kBH * kL * kL;    // 67,108,864

constexpr int kGemmBufFloats  = 128 * 36;                   // 4,608
constexpr int kGemmSmemBytes  = 4 * kGemmBufFloats * 4;     // 73,728 B

constexpr int kQeSmemBytes    = 2 * 128 * 68 * 4;           // 69,632 B
constexpr int kScoreSmemBytes = 2 * 128 * 68 * 4;           // 69,632 B
constexpr int kPvSmemFloats   = 128 * 132 + 64 * 132 + 128;
constexpr int kPvSmemBytes    = kPvSmemFloats * 4;          // 101,888 B

constexpr float kQScale = 0.125f * 1.4426950408889634f;
}

// Scratch (device globals; no allocations allowed)
__device__ float  g_q[kBH * kL * kHD];
__device__ float  g_k[kBH * kL * kHD];
__device__ float  g_v[kBH * kL * kHD];
__device__ float  g_ctx[kBH * kL * kHD];
__device__ __half g_qe[kBH * kL * kL];       // QE skew, fp16
__device__ __half g_ph[kBH * kL * kL];       // unnormalized p, fp16
__device__ float  g_rspart[kBH * kL * 8];
__device__ float  g_wt[4 * kD * kD];
__device__ float  g_fb[kAttnElems];          // fallback attn sink

// ---------------------------------------------------------------------------
// Helpers
// ---------------------------------------------------------------------------
__device__ __forceinline__ uint32_t f2tf32(float x) {
    uint32_t r;
    asm("cvt.rna.tf32.f32 %0, %1;" : "=r"(r) : "f"(x));
    return r;
}
__device__ __forceinline__ float tf32f(float x) {
    return __uint_as_float(f2tf32(x));
}
__device__ __forceinline__ void mma_tf32(float* c, const uint32_t* a, const uint32_t* b) {
    asm volatile(
        "mma.sync.aligned.m16n8k8.row.col.f32.tf32.tf32.f32 "
        "{%0,%1,%2,%3}, {%4,%5,%6,%7}, {%8,%9}, {%0,%1,%2,%3};"
        : "+f"(c[0]), "+f"(c[1]), "+f"(c[2]), "+f"(c[3])
        : "r"(a[0]), "r"(a[1]), "r"(a[2]), "r"(a[3]), "r"(b[0]), "r"(b[1]));
}
__device__ __forceinline__ float exp2p(float x) {
    float t = x + 12582912.0f;
    int   n = __float_as_int(t) - 0x4B400000;
    float f = x - (t - 12582912.0f);
    float r = 1.3333558e-3f;
    r = fmaf(r, f, 9.6181291e-3f);
    r = fmaf(r, f, 5.5504109e-2f);
    r = fmaf(r, f, 2.4022651e-1f);
    r = fmaf(r, f, 6.9314718e-1f);
    r = fmaf(r, f, 1.0f);
    return __int_as_float(__float_as_int(r) + (n << 23));
}

// ---------------------------------------------------------------------------
// Zero-fill of strictly-upper attn tiles. grid(28, 64). Independent of all
// other work; launched first on the side stream and hidden under qkv.
// ---------------------------------------------------------------------------
__global__ void __launch_bounds__(256)
zfill_kernel(float* __restrict__ attn) {
    int j = blockIdx.x, zlt = 0;
    while (j >= 7 - zlt) { j -= 7 - zlt; zlt++; }
    const int zmt = zlt + 1 + j;
    const int bh  = blockIdx.y;
    float4* zdst = reinterpret_cast<float4*>(
        attn + (size_t)(bh * kL + zlt * 128) * kL + zmt * 128);
    const float4 z4 = make_float4(0.f, 0.f, 0.f, 0.f);
    const int tid = threadIdx.x;
    #pragma unroll
    for (int t = 0; t < 16; t++) {
        int idx = tid + t * 256;
        int r = idx >> 5, c4 = idx & 31;
        __stcs(&zdst[r * (kL / 4) + c4], z4);
    }
}

// ---------------------------------------------------------------------------
// Weight transpose: g_wt[z][n][k] = W_z[k][n]
// ---------------------------------------------------------------------------
__global__ void wt_kernel(const float* __restrict__ Wq, const float* __restrict__ Wk,
                          const float* __restrict__ Wv, const float* __restrict__ Wo) {
    __shared__ float t[32][33];
    const int z = blockIdx.z;
    const float* W = (z == 0) ? Wq : (z == 1) ? Wk : (z == 2) ? Wv : Wo;
    float* T = g_wt + z * kD * kD;
    const int k0 = blockIdx.x * 32, n0 = blockIdx.y * 32;
    #pragma unroll
    for (int i = 0; i < 4; i++)
        t[threadIdx.y + i * 8][threadIdx.x] =
            W[(k0 + threadIdx.y + i * 8) * kD + n0 + threadIdx.x];
    __syncthreads();
    #pragma unroll
    for (int i = 0; i < 4; i++)
        T[(n0 + threadIdx.y + i * 8) * kD + k0 + threadIdx.x] =
            t[threadIdx.x][threadIdx.y + i * 8];
}

// ---------------------------------------------------------------------------
// mma.sync tf32 GEMM: C[128x128] = A[128x512] @ Wt[128x512]^T + bias, scaled.
// ---------------------------------------------------------------------------
__device__ __forceinline__ void gemm_mma(const float* __restrict__ A,
                                         const float* __restrict__ Wt,
                                         const float* __restrict__ bias,
                                         float* __restrict__ O,
                                         int row0, int col0, float scale,
                                         bool gather, bool headt) {
    extern __shared__ float sm[];
    const int tid  = threadIdx.x;
    const int wid  = tid >> 5;
    const int lane = tid & 31;
    const int wm   = (wid >> 2) * 64;
    const int wn   = (wid & 3) * 32;

    float c[4][4][4];
    #pragma unroll
    for (int mt = 0; mt < 4; mt++)
        #pragma unroll
        for (int nt = 0; nt < 4; nt++)
            #pragma unroll
            for (int e = 0; e < 4; e++) c[mt][nt][e] = 0.f;

    float4 va[4], vb[4];
    auto gload = [&](int k0) {
        #pragma unroll
        for (int t = 0; t < 4; t++) {
            const int idx = tid + t * 256;
            const int r = idx >> 3, c4 = idx & 7;
            if (gather) {
                int rg = row0 + r;
                int bb = rg >> 10, l = rg & 1023;
                int k = k0 + c4 * 4;
                int h = k >> 6, hd = k & 63;
                va[t] = *reinterpret_cast<const float4*>(
                    &g_ctx[(((bb * kH + h) * kL + l) * kHD) + hd]);
            } else {
                va[t] = *reinterpret_cast<const float4*>(&A[(row0 + r) * kD + k0 + c4 * 4]);
            }
            vb[t] = *reinterpret_cast<const float4*>(&Wt[(col0 + r) * kD + k0 + c4 * 4]);
        }
    };
    auto sts = [&](int buf) {
        float* As = sm + buf * kGemmBufFloats;
        float* Bs = sm + (2 + buf) * kGemmBufFloats;
        #pragma unroll
        for (int t = 0; t < 4; t++) {
            const int idx = tid + t * 256;
            const int r = idx >> 3, c4 = idx & 7;
            float4 wa, wb;
            wa.x = tf32f(va[t].x); wa.y = tf32f(va[t].y);
            wa.z = tf32f(va[t].z); wa.w = tf32f(va[t].w);
            wb.x = tf32f(vb[t].x); wb.y = tf32f(vb[t].y);
            wb.z = tf32f(vb[t].z); wb.w = tf32f(vb[t].w);
            *reinterpret_cast<float4*>(&As[r * 36 + c4 * 4]) = wa;
            *reinterpret_cast<float4*>(&Bs[r * 36 + c4 * 4]) = wb;
        }
    };
    auto compute = [&](int buf) {
        const float* As = sm + buf * kGemmBufFloats;
        const float* Bs = sm + (2 + buf) * kGemmBufFloats;
        const int r0 = wm + (lane >> 2);
        const int n0 = wn + (lane >> 2);
        #pragma unroll
        for (int k8 = 0; k8 < 4; k8++) {
            const int kc = k8 * 8 + (lane & 3);
            uint32_t a[4][4], b[4][2];
            #pragma unroll
            for (int mt = 0; mt < 4; mt++) {
                a[mt][0] = __float_as_uint(As[(r0 + mt * 16) * 36 + kc]);
                a[mt][1] = __float_as_uint(As[(r0 + mt * 16 + 8) * 36 + kc]);
                a[mt][2] = __float_as_uint(As[(r0 + mt * 16) * 36 + kc + 4]);
                a[mt][3] = __float_as_uint(As[(r0 + mt * 16 + 8) * 36 + kc + 4]);
            }
            #pragma unroll
            for (int nt = 0; nt < 4; nt++) {
                b[nt][0] = __float_as_uint(Bs[(n0 + nt * 8) * 36 + kc]);
                b[nt][1] = __float_as_uint(Bs[(n0 + nt * 8) * 36 + kc + 4]);
            }
            #pragma unroll
            for (int mt = 0; mt < 4; mt++)
                #pragma unroll
                for (int nt = 0; nt < 4; nt++)
                    mma_tf32(c[mt][nt], a[mt], b[nt]);
        }
    };

    gload(0);
    sts(0);
    __syncthreads();
    for (int it = 0; it < 16; it++) {
        if (it < 15) gload((it + 1) * 32);
        compute(it & 1);
        if (it < 15) {
            __syncthreads();
            sts((it + 1) & 1);
            __syncthreads();
        }
    }

    #pragma unroll
    for (int mt = 0; mt < 4; mt++) {
        #pragma unroll
        for (int nt = 0; nt < 4; nt++) {
            const int row = row0 + wm + mt * 16 + (lane >> 2);
            const int col = col0 + wn + nt * 8 + 2 * (lane & 3);
            const float b0 = bias[col], b1 = bias[col + 1];
            #pragma unroll
            for (int half = 0; half < 2; half++) {
                const int r = row + half * 8;
                float2 v;
                v.x = (c[mt][nt][half * 2 + 0] + b0) * scale;
                v.y = (c[mt][nt][half * 2 + 1] + b1) * scale;
                if (headt) {
                    const int bb = r >> 10, l = r & 1023;
                    const int h = col >> 6, hd = col & 63;
                    *reinterpret_cast<float2*>(
                        &O[(((bb * kH + h) * kL + l) * kHD) + hd]) = v;
                } else {
                    __stcs(reinterpret_cast<float2*>(&O[r * kD + col]), v);
                }
            }
        }
    }
}

__global__ void __launch_bounds__(256, 2)
qkv_tc_kernel(const float* __restrict__ xq, const float* __restrict__ xk,
              const float* __restrict__ xv,
              const float* __restrict__ bq, const float* __restrict__ bk,
              const float* __restrict__ bv, int zoff) {
    const int z = blockIdx.z + zoff;
    const float* X    = (z == 0) ? xq : (z == 1) ? xk : xv;
    const float* bias = (z == 0) ? bq : (z == 1) ? bk : bv;
    float* O          = (z == 0) ? g_q : (z == 1) ? g_k : g_v;
    const float scale = (z == 0) ? kQScale : 1.0f;
    gemm_mma(X, g_wt + z * kD * kD, bias, O,
             blockIdx.y * 128, blockIdx.x * 128, scale, false, true);
}

__global__ void __launch_bounds__(256, 2)
proj_tc_kernel(const float* __restrict__ bo, float* __restrict__ out) {
    gemm_mma(nullptr, g_wt + 3 * kD * kD, bo, out,
             blockIdx.y * 128, blockIdx.x * 128, 1.0f, true, false);
}

// ---------------------------------------------------------------------------
// QE kernel (mma.sync): fp16 output, causal-band tile skip.
// ---------------------------------------------------------------------------
__global__ void __launch_bounds__(256, 2)
qe_mma_kernel(const float* __restrict__ relE) {
    const int r0    = blockIdx.x * 128;
    const int row0  = blockIdx.y * 128;
    const int l0loc = row0 & (kL - 1);
    if (l0loc + r0 < 769) return;

    extern __shared__ float sm[];
    float* Qs = sm;                  // [128][68]
    float* Es = sm + 128 * 68;       // [128][68]

    const int tid  = threadIdx.x;
    const int wid  = tid >> 5;
    const int lane = tid & 31;
    const int wm   = (wid >> 2) * 64;
    const int wn   = (wid & 3) * 32;

    #pragma unroll
    for (int t = 0; t < 8; t++) {
        int idx = tid + t * 256;
        int r = idx >> 4, d4 = idx & 15;
        float4 q4 = *reinterpret_cast<const float4*>(&g_q[(row0 + r) * kHD + d4 * 4]);
        float4 e4 = *reinterpret_cast<const float4*>(&relE[(r0 + r) * kHD + d4 * 4]);
        float4 wq, we;
        wq.x = tf32f(q4.x); wq.y = tf32f(q4.y); wq.z = tf32f(q4.z); wq.w = tf32f(q4.w);
        we.x = tf32f(e4.x); we.y = tf32f(e4.y); we.z = tf32f(e4.z); we.w = tf32f(e4.w);
        *reinterpret_cast<float4*>(&Qs[r * 68 + d4 * 4]) = wq;
        *reinterpret_cast<float4*>(&Es[r * 68 + d4 * 4]) = we;
    }
    __syncthreads();

    float c[4][4][4];
    #pragma unroll
    for (int mt = 0; mt < 4; mt++)
        #pragma unroll
        for (int nt = 0; nt < 4; nt++)
            #pragma unroll
            for (int e = 0; e < 4; e++) c[mt][nt][e] = 0.f;

    const int r0a = wm + (lane >> 2);
    const int n0b = wn + (lane >> 2);
    #pragma unroll
    for (int k8 = 0; k8 < 8; k8++) {
        const int kc = k8 * 8 + (lane & 3);
        uint32_t a[4][4], b[4][2];
        #pragma unroll
        for (int mt = 0; mt < 4; mt++) {
            a[mt][0] = __float_as_uint(Qs[(r0a + mt * 16) * 68 + kc]);
            a[mt][1] = __float_as_uint(Qs[(r0a + mt * 16 + 8) * 68 + kc]);
            a[mt][2] = __float_as_uint(Qs[(r0a + mt * 16) * 68 + kc + 4]);
            a[mt][3] = __float_as_uint(Qs[(r0a + mt * 16 + 8) * 68 + kc + 4]);
        }
        #pragma unroll
        for (int nt = 0; nt < 4; nt++) {
            b[nt][0] = __float_as_uint(Es[(n0b + nt * 8) * 68 + kc]);
            b[nt][1] = __float_as_uint(Es[(n0b + nt * 8) * 68 + kc + 4]);
        }
        #pragma unroll
        for (int mt = 0; mt < 4; mt++)
            #pragma unroll
            for (int nt = 0; nt < 4; nt++)
                mma_tf32(c[mt][nt], a[mt], b[nt]);
    }

    #pragma unroll
    for (int mt = 0; mt < 4; mt++)
        #pragma unroll
        for (int nt = 0; nt < 4; nt++) {
            const int row = row0 + wm + mt * 16 + (lane >> 2);
            const int col = r0 + wn + nt * 8 + 2 * (lane & 3);
            #pragma unroll
            for (int half = 0; half < 2; half++) {
                __half2 v = __floats2half2_rn(c[mt][nt][half * 2],
                                              c[mt][nt][half * 2 + 1]);
                *reinterpret_cast<__half2*>(
                    &g_qe[(size_t)(row + half * 8) * kL + col]) = v;
            }
        }
}

// ---------------------------------------------------------------------------
// score kernel: one CTA per causal 128x128 tile. grid(36, nbh).
// ---------------------------------------------------------------------------
__global__ void __launch_bounds__(256, 2)
score_mma_kernel(int bh0) {
    extern __shared__ float sm[];
    float* Qs = sm;                  // [128][68]
    float* Ks = sm + 128 * 68;       // [128][68]

    const int ti = blockIdx.x;
    int lt = 0;
    #pragma unroll
    for (int t = 1; t < 8; t++)
        if (ti >= (t * (t + 1)) / 2) lt = t;
    const int mt_t = ti - (lt * (lt + 1)) / 2;
    const int bh = blockIdx.y + bh0;
    const int l0 = lt * 128;
    const int m0 = mt_t * 128;

    const int tid  = threadIdx.x;
    const int wid  = tid >> 5;
    const int lane = tid & 31;
    const int wm   = (wid >> 2) * 64;
    const int wn   = (wid & 3) * 32;

    #pragma unroll
    for (int t = 0; t < 8; t++) {
        int idx = tid + t * 256;
        int r = idx >> 4, d4 = idx & 15;
        float4 q4 = *reinterpret_cast<const float4*>(
            &g_q[(bh * kL + l0 + r) * kHD + d4 * 4]);
        float4 k4 = *reinterpret_cast<const float4*>(
            &g_k[(bh * kL + m0 + r) * kHD + d4 * 4]);
        float4 wq, wk;
        wq.x = tf32f(q4.x); wq.y = tf32f(q4.y); wq.z = tf32f(q4.z); wq.w = tf32f(q4.w);
        wk.x = tf32f(k4.x); wk.y = tf32f(k4.y); wk.z = tf32f(k4.z); wk.w = tf32f(k4.w);
        *reinterpret_cast<float4*>(&Qs[r * 68 + d4 * 4]) = wq;
        *reinterpret_cast<float4*>(&Ks[r * 68 + d4 * 4]) = wk;
    }
    __syncthreads();

    float c[4][4][4];
    #pragma unroll
    for (int mt = 0; mt < 4; mt++)
        #pragma unroll
        for (int nt = 0; nt < 4; nt++)
            #pragma unroll
            for (int e = 0; e < 4; e++) c[mt][nt][e] = 0.f;

    const int r0a = wm + (lane >> 2);
    const int n0b = wn + (lane >> 2);
    #pragma unroll
    for (int k8 = 0; k8 < 8; k8++) {
        const int kc = k8 * 8 + (lane & 3);
        uint32_t a[4][4], b[4][2];
        #pragma unroll
        for (int mt = 0; mt < 4; mt++) {
            a[mt][0] = __float_as_uint(Qs[(r0a + mt * 16) * 68 + kc]);
            a[mt][1] = __float_as_uint(Qs[(r0a + mt * 16 + 8) * 68 + kc]);
            a[mt][2] = __float_as_uint(Qs[(r0a + mt * 16) * 68 + kc + 4]);
            a[mt][3] = __float_as_uint(Qs[(r0a + mt * 16 + 8) * 68 + kc + 4]);
        }
        #pragma unroll
        for (int nt = 0; nt < 4; nt++) {
            b[nt][0] = __float_as_uint(Ks[(n0b + nt * 8) * 68 + kc]);
            b[nt][1] = __float_as_uint(Ks[(n0b + nt * 8) * 68 + kc + 4]);
        }
        #pragma unroll
        for (int mt = 0; mt < 4; mt++)
            #pragma unroll
            for (int nt = 0; nt < 4; nt++)
                mma_tf32(c[mt][nt], a[mt], b[nt]);
    }
    __syncthreads();                 // Qs/Ks dead; alias as fp16 stage + rs

    __half* stageH = reinterpret_cast<__half*>(sm);   // [128][136] halves
    float*  rs     = sm + (128 * 136 * 2) / 4;        // [128][4] floats

    #pragma unroll
    for (int mt = 0; mt < 4; mt++) {
        #pragma unroll
        for (int half = 0; half < 2; half++) {
            const int row = wm + mt * 16 + (lane >> 2) + half * 8;
            const int l   = l0 + row;
            const __half* qe_row = g_qe + (size_t)(bh * kL + l) * kL + (1023 - l);
            float rp = 0.f;
            #pragma unroll
            for (int nt = 0; nt < 4; nt++) {
                const int col = wn + nt * 8 + 2 * (lane & 3);
                const int m   = m0 + col;
                float v0 = 0.f, v1 = 0.f;
                if (m <= l)
                    v0 = exp2p(c[mt][nt][half * 2 + 0] +
                               __half2float(__ldcs(qe_row + m)));
                if (m + 1 <= l)
                    v1 = exp2p(c[mt][nt][half * 2 + 1] +
                               __half2float(__ldcs(qe_row + m + 1)));
                *reinterpret_cast<__half2*>(&stageH[row * 136 + col]) =
                    __floats2half2_rn(v0, v1);
                rp += v0 + v1;
            }
            rp += __shfl_xor_sync(0xffffffffu, rp, 1);
            rp += __shfl_xor_sync(0xffffffffu, rp, 2);
            if ((lane & 3) == 0) rs[row * 4 + (wid & 3)] = rp;
        }
    }
    __syncthreads();

    if (tid < 128) {
        float s = rs[tid * 4] + rs[tid * 4 + 1] + rs[tid * 4 + 2] + rs[tid * 4 + 3];
        g_rspart[(size_t)(bh * kL + l0 + tid) * 8 + mt_t] = s;
    }

    __half* dst = g_ph + (size_t)(bh * kL + l0) * kL + m0;
    #pragma unroll
    for (int t = 0; t < 8; t++) {
        int idx = tid + t * 256;
        int r = idx >> 4, c8 = idx & 15;
        uint4 v = *reinterpret_cast<const uint4*>(&stageH[r * 136 + c8 * 8]);
        *reinterpret_cast<uint4*>(dst + (size_t)r * kL + c8 * 8) = v;
    }
}

// ---------------------------------------------------------------------------
// pv kernel: one CTA per (bh, 128 rows). grid(8, nbh), 2 CTA/SM.
// ---------------------------------------------------------------------------
__global__ void __launch_bounds__(256, 2)
pv_mma_kernel(float* __restrict__ attn, int bh0) {
    extern __shared__ float sm[];
    float* As    = sm;                       // [128][132]
    float* vst   = As + 128 * 132;           // [64][132]
    float* rsinv = vst + 64 * 132;           // [128]

    const int lt  = 7 - blockIdx.x;          // heavy CTAs first
    const int bh  = blockIdx.y + bh0;
    const int l0  = lt * 128;
    const int tid = threadIdx.x;
    const int wid  = tid >> 5;
    const int lane = tid & 31;
    const int wm   = (wid >> 2) * 64;
    const int wn   = (wid & 3) * 16;

    if (tid < 128) {
        float s = 0.f;
        for (int mt = 0; mt <= lt; mt++)
            s += g_rspart[(size_t)(bh * kL + l0 + tid) * 8 + mt];
        rsinv[tid] = 1.f / s;
    }
    __syncthreads();

    float c[4][2][4];
    #pragma unroll
    for (int mt = 0; mt < 4; mt++)
        #pragma unroll
        for (int nt = 0; nt < 2; nt++)
            #pragma unroll
            for (int e = 0; e < 4; e++) c[mt][nt][e] = 0.f;

    for (int mtile = 0; mtile <= lt; mtile++) {
        #pragma unroll
        for (int t = 0; t < 8; t++) {
            int idx = tid + t * 256;
            int m = idx >> 4, d4 = idx & 15;
            float4 v4 = *reinterpret_cast<const float4*>(
                &g_v[(bh * kL + mtile * 128 + m) * kHD + d4 * 4]);
            vst[(d4 * 4 + 0) * 132 + m] = tf32f(v4.x);
            vst[(d4 * 4 + 1) * 132 + m] = tf32f(v4.y);
            vst[(d4 * 4 + 2) * 132 + m] = tf32f(v4.z);
            vst[(d4 * 4 + 3) * 132 + m] = tf32f(v4.w);
        }
        {
            const __half* src = g_ph + (size_t)(bh * kL + l0) * kL + mtile * 128;
            float4* pa = reinterpret_cast<float4*>(
                attn + (size_t)(bh * kL + l0) * kL + mtile * 128);
            #pragma unroll
            for (int t = 0; t < 8; t++) {
                int idx = tid + t * 256;
                int r = idx >> 4, c8 = idx & 15;
                uint4 raw = __ldcs(reinterpret_cast<const uint4*>(
                    src + (size_t)r * kL + c8 * 8));
                const float inv = rsinv[r];
                float2 f0 = __half22float2(*reinterpret_cast<__half2*>(&raw.x));
                float2 f1 = __half22float2(*reinterpret_cast<__half2*>(&raw.y));
                float2 f2 = __half22float2(*reinterpret_cast<__half2*>(&raw.z));
                float2 f3 = __half22float2(*reinterpret_cast<__half2*>(&raw.w));
                float4 o0 = make_float4(f0.x * inv, f0.y * inv, f1.x * inv, f1.y * inv);
                float4 o1 = make_float4(f2.x * inv, f2.y * inv, f3.x * inv, f3.y * inv);
                __stcs(&pa[r * (kL / 4) + c8 * 2 + 0], o0);
                __stcs(&pa[r * (kL / 4) + c8 * 2 + 1], o1);
                float* st = &As[r * 132 + c8 * 8];
                st[0] = tf32f(o0.x); st[1] = tf32f(o0.y);
                st[2] = tf32f(o0.z); st[3] = tf32f(o0.w);
                st[4] = tf32f(o1.x); st[5] = tf32f(o1.y);
                st[6] = tf32f(o1.z); st[7] = tf32f(o1.w);
            }
        }
        __syncthreads();

        const int r0a = wm + (lane >> 2);
        const int n0b = wn + (lane >> 2);
        #pragma unroll
        for (int k8 = 0; k8 < 16; k8++) {
            const int kc = k8 * 8 + (lane & 3);
            uint32_t a[4][4], b[2][2];
            #pragma unroll
            for (int mt = 0; mt < 4; mt++) {
                a[mt][0] = __float_as_uint(As[(r0a + mt * 16) * 132 + kc]);
                a[mt][1] = __float_as_uint(As[(r0a + mt * 16 + 8) * 132 + kc]);
                a[mt][2] = __float_as_uint(As[(r0a + mt * 16) * 132 + kc + 4]);
                a[mt][3] = __float_as_uint(As[(r0a + mt * 16 + 8) * 132 + kc + 4]);
            }
            #pragma unroll
            for (int nt = 0; nt < 2; nt++) {
                b[nt][0] = __float_as_uint(vst[(n0b + nt * 8) * 132 + kc]);
                b[nt][1] = __float_as_uint(vst[(n0b + nt * 8) * 132 + kc + 4]);
            }
            #pragma unroll
            for (int mt = 0; mt < 4; mt++)
                #pragma unroll
                for (int nt = 0; nt < 2; nt++)
                    mma_tf32(c[mt][nt], a[mt], b[nt]);
        }
        __syncthreads();
    }

    #pragma unroll
    for (int mt = 0; mt < 4; mt++)
        #pragma unroll
        for (int nt = 0; nt < 2; nt++) {
            const int d = wn + nt * 8 + 2 * (lane & 3);
            #pragma unroll
            for (int half = 0; half < 2; half++) {
                const int row = l0 + wm + mt * 16 + (lane >> 2) + half * 8;
                float2 v = make_float2(c[mt][nt][half * 2], c[mt][nt][half * 2 + 1]);
                *reinterpret_cast<float2*>(
                    &g_ctx[(size_t)(bh * kL + row) * kHD + d]) = v;
            }
        }
}

// ---------------------------------------------------------------------------
extern "C" void kernel_launch(void* const* d_in, const int* in_sizes, int n_in,
                              void* d_out, int out_size) {
    const float* xq   = (const float*)d_in[0];
    const float* xk   = (const float*)d_in[1];
    const float* xv   = (const float*)d_in[2];
    // d_in[3] = mask (unused: causal mask applied analytically)
    const float* Wq   = (const float*)d_in[4];
    const float* bq   = (const float*)d_in[5];
    const float* Wk   = (const float*)d_in[6];
    const float* bk   = (const float*)d_in[7];
    const float* Wv   = (const float*)d_in[8];
    const float* bv   = (const float*)d_in[9];
    const float* Wo   = (const float*)d_in[10];
    const float* bo   = (const float*)d_in[11];
    const float* relE = (const float*)d_in[12];

    float* out = (float*)d_out;
    float* attn;
    if (out_size >= kOutElems + kAttnElems) {
        attn = out + kOutElems;
    } else {
        cudaGetSymbolAddress((void**)&attn, g_fb);   // never expected in practice
    }

    // One-time infra (created on the uncaptured correctness call; identical
    // work is enqueued on every call -> deterministic & graph-capturable).
    static cudaStream_t s1 = nullptr;
    static cudaEvent_t  e0, eQ, eKV, eQE, eSA, eP1;
    if (s1 == nullptr) {
        cudaStreamCreateWithFlags(&s1, cudaStreamNonBlocking);
        cudaEventCreateWithFlags(&e0,  cudaEventDisableTiming);
        cudaEventCreateWithFlags(&eQ,  cudaEventDisableTiming);
        cudaEventCreateWithFlags(&eKV, cudaEventDisableTiming);
        cudaEventCreateWithFlags(&eQE, cudaEventDisableTiming);
        cudaEventCreateWithFlags(&eSA, cudaEventDisableTiming);
        cudaEventCreateWithFlags(&eP1, cudaEventDisableTiming);
        cudaFuncSetAttribute(qe_mma_kernel,
                             cudaFuncAttributeMaxDynamicSharedMemorySize, kQeSmemBytes);
        cudaFuncSetAttribute(score_mma_kernel,
                             cudaFuncAttributeMaxDynamicSharedMemorySize, kScoreSmemBytes);
        cudaFuncSetAttribute(pv_mma_kernel,
                             cudaFuncAttributeMaxDynamicSharedMemorySize, kPvSmemBytes);
        cudaFuncSetAttribute(qkv_tc_kernel,
                             cudaFuncAttributeMaxDynamicSharedMemorySize, kGemmSmemBytes);
        cudaFuncSetAttribute(proj_tc_kernel,
                             cudaFuncAttributeMaxDynamicSharedMemorySize, kGemmSmemBytes);
    }

    // ---- fork side stream ----
    cudaEventRecord(e0, 0);
    cudaStreamWaitEvent(s1, e0, 0);

    // s1: zero-fill upper attn triangle (independent of everything)
    zfill_kernel<<<dim3(28, kBH), 256, 0, s1>>>(attn);

    // s0: weight transpose, then q projection
    wt_kernel<<<dim3(16, 16, 4), dim3(32, 8)>>>(Wq, Wk, Wv, Wo);
    qkv_tc_kernel<<<dim3(kD / 128, (kB * kL) / 128, 1), 256, kGemmSmemBytes>>>(
        xq, xk, xv, bq, bk, bv, 0);
    cudaEventRecord(eQ, 0);
    // s0: k, v projections
    qkv_tc_kernel<<<dim3(kD / 128, (kB * kL) / 128, 2), 256, kGemmSmemBytes>>>(
        xq, xk, xv, bq, bk, bv, 1);
    cudaEventRecord(eKV, 0);

    // s1: qe (needs q only) — overlaps k/v projections
    cudaStreamWaitEvent(s1, eQ, 0);
    qe_mma_kernel<<<dim3(kL / 128, (kBH * kL) / 128), 256, kQeSmemBytes, s1>>>(relE);
    cudaEventRecord(eQE, s1);

    // s0: score half A (bh 0..31), then pv half A
    cudaStreamWaitEvent(0, eQE, 0);
    score_mma_kernel<<<dim3(36, kBH / 2), 256, kScoreSmemBytes>>>(0);
    cudaEventRecord(eSA, 0);
    pv_mma_kernel<<<dim3(8, kBH / 2), 256, kPvSmemBytes>>>(attn, 0);

    // s1: score half B (staggered; overlaps pv half A), then pv half B
    cudaStreamWaitEvent(s1, eKV, 0);
    cudaStreamWaitEvent(s1, eSA, 0);
    score_mma_kernel<<<dim3(36, kBH / 2), 256, kScoreSmemBytes, s1>>>(kBH / 2);
    pv_mma_kernel<<<dim3(8, kBH / 2), 256, kPvSmemBytes, s1>>>(attn, kBH / 2);
    cudaEventRecord(eP1, s1);

    // ---- join and final projection ----
    cudaStreamWaitEvent(0, eP1, 0);
    proj_tc_kernel<<<dim3(kD / 128, (kB * kL) / 128), 256, kGemmSmemBytes>>>(bo, out);
}